// round 1
// baseline (speedup 1.0000x reference)
#include <cuda_runtime.h>
#include <math_constants.h>

#define TOKENS (8 * 2048)
#define EDIM   512
#define NHEAD  64
#define DK     8

// Scratch: permuted attention output "mid" = (16384 rows x 512 cols) fp32 = 32 MB
__device__ float g_mid[(size_t)TOKENS * EDIM];

// ---------------------------------------------------------------------------
// Kernel A: per-token quantum-projection attention.
// 256 threads = 4 tokens/CTA, 64 threads (one per head) per token.
// All smem proj reads are warp-uniform broadcasts (conflict-free).
// ---------------------------------------------------------------------------
__global__ __launch_bounds__(256, 2) void qattn_kernel(const float* __restrict__ x,
                                                       const float* __restrict__ theta) {
    __shared__ float sproj[4][EDIM];

    const int tl = threadIdx.x >> 6;   // token slot in CTA: 0..3
    const int h  = threadIdx.x & 63;   // head
    const int token = (blockIdx.x << 2) + tl;

    // theta (8 values, broadcast)
    float th[8];
    {
        const float4 t0 = ((const float4*)theta)[0];
        const float4 t1 = ((const float4*)theta)[1];
        th[0] = t0.x; th[1] = t0.y; th[2] = t0.z; th[3] = t0.w;
        th[4] = t1.x; th[5] = t1.y; th[6] = t1.z; th[7] = t1.w;
    }

    // proj[h, :] = cos(x + theta)
    float p[8];
    {
        const float4* xp = (const float4*)(x + (size_t)token * EDIM + h * DK);
        const float4 a0 = xp[0], a1 = xp[1];
        p[0] = __cosf(a0.x + th[0]); p[1] = __cosf(a0.y + th[1]);
        p[2] = __cosf(a0.z + th[2]); p[3] = __cosf(a0.w + th[3]);
        p[4] = __cosf(a1.x + th[4]); p[5] = __cosf(a1.y + th[5]);
        p[6] = __cosf(a1.z + th[6]); p[7] = __cosf(a1.w + th[7]);
    }
    {
        float4* sp = (float4*)&sproj[tl][h * DK];
        sp[0] = make_float4(p[0], p[1], p[2], p[3]);
        sp[1] = make_float4(p[4], p[5], p[6], p[7]);
    }
    __syncthreads();

    // scores row h: dot(p, proj[g]) / sqrt(8)    (s[] fully in registers)
    const float scale = 0.35355339059327373f;
    float s[NHEAD];
    float m = -CUDART_INF_F;
    #pragma unroll
    for (int g = 0; g < NHEAD; g++) {
        const float4* qp = (const float4*)&sproj[tl][g * DK];
        const float4 q0 = qp[0], q1 = qp[1];
        float dot = p[0] * q0.x + p[1] * q0.y + p[2] * q0.z + p[3] * q0.w
                  + p[4] * q1.x + p[5] * q1.y + p[6] * q1.z + p[7] * q1.w;
        dot *= scale;
        s[g] = dot;
        m = fmaxf(m, dot);
    }

    // softmax (unnormalized weights in s[], normalize at the end)
    float sum = 0.f;
    #pragma unroll
    for (int g = 0; g < NHEAD; g++) {
        const float e = __expf(s[g] - m);
        s[g] = e;
        sum += e;
    }
    const float inv = 1.0f / sum;

    // attn row h = (weights @ proj)
    float acc[8] = {0.f, 0.f, 0.f, 0.f, 0.f, 0.f, 0.f, 0.f};
    #pragma unroll
    for (int g = 0; g < NHEAD; g++) {
        const float4* qp = (const float4*)&sproj[tl][g * DK];
        const float4 q0 = qp[0], q1 = qp[1];
        const float w = s[g];
        acc[0] += w * q0.x; acc[1] += w * q0.y; acc[2] += w * q0.z; acc[3] += w * q0.w;
        acc[4] += w * q1.x; acc[5] += w * q1.y; acc[6] += w * q1.z; acc[7] += w * q1.w;
    }

    // permuted store:  mid[b, h*32 + s/64, (s%64)*8 + d]
    const int b  = token >> 11;          // /2048
    const int sb = token & 2047;
    const size_t row = (size_t)(b * 2048) + (size_t)(h * 32) + (size_t)(sb >> 6);
    float* op = g_mid + row * EDIM + (size_t)((sb & 63) * DK);
    ((float4*)op)[0] = make_float4(acc[0] * inv, acc[1] * inv, acc[2] * inv, acc[3] * inv);
    ((float4*)op)[1] = make_float4(acc[4] * inv, acc[5] * inv, acc[6] * inv, acc[7] * inv);
}

// ---------------------------------------------------------------------------
// Kernel B: out[16384,512] = mid @ W^T + bias   (W is [512 out, 512 in], K-major)
// Classic 128x128x8 SGEMM, 256 threads, 8x8 microtile, padded smem.
// ---------------------------------------------------------------------------
__global__ __launch_bounds__(256, 2) void out_gemm_kernel(const float* __restrict__ W,
                                                          const float* __restrict__ bias,
                                                          float* __restrict__ out) {
    __shared__ float As[8][132];   // +4 pad: conflict-free stores
    __shared__ float Bs[8][132];

    const int tid = threadIdx.x;
    const int rowBase = blockIdx.y * 128;   // over 16384 rows of mid
    const int colBase = blockIdx.x * 128;   // over 512 output cols

    const int lr = tid >> 1;          // 0..127 : row within tile
    const int lk = (tid & 1) * 4;     // 0 or 4 : k offset

    const float* Aptr = g_mid + (size_t)(rowBase + lr) * EDIM + lk;
    const float* Bptr = W     + (size_t)(colBase + lr) * EDIM + lk;

    const int tx = tid & 15;   // col group
    const int ty = tid >> 4;   // row group

    float acc[8][8];
    #pragma unroll
    for (int i = 0; i < 8; i++)
        #pragma unroll
        for (int j = 0; j < 8; j++) acc[i][j] = 0.f;

    for (int k0 = 0; k0 < EDIM; k0 += 8) {
        const float4 av = *(const float4*)(Aptr + k0);
        const float4 bv = *(const float4*)(Bptr + k0);
        __syncthreads();   // previous iteration's reads done before overwrite
        As[lk + 0][lr] = av.x; As[lk + 1][lr] = av.y;
        As[lk + 2][lr] = av.z; As[lk + 3][lr] = av.w;
        Bs[lk + 0][lr] = bv.x; Bs[lk + 1][lr] = bv.y;
        Bs[lk + 2][lr] = bv.z; Bs[lk + 3][lr] = bv.w;
        __syncthreads();

        #pragma unroll
        for (int kk = 0; kk < 8; kk++) {
            float a[8], b[8];
            *(float4*)(a)     = *(const float4*)&As[kk][ty * 8];
            *(float4*)(a + 4) = *(const float4*)&As[kk][ty * 8 + 4];
            *(float4*)(b)     = *(const float4*)&Bs[kk][tx * 8];
            *(float4*)(b + 4) = *(const float4*)&Bs[kk][tx * 8 + 4];
            #pragma unroll
            for (int i = 0; i < 8; i++)
                #pragma unroll
                for (int j = 0; j < 8; j++)
                    acc[i][j] += a[i] * b[j];
        }
    }

    // epilogue: + bias, write out
    float bb[8];
    *(float4*)(bb)     = *(const float4*)&bias[colBase + tx * 8];
    *(float4*)(bb + 4) = *(const float4*)&bias[colBase + tx * 8 + 4];

    #pragma unroll
    for (int i = 0; i < 8; i++) {
        const size_t r = (size_t)(rowBase + ty * 8 + i);
        float* op = out + r * EDIM + colBase + tx * 8;
        ((float4*)op)[0] = make_float4(acc[i][0] + bb[0], acc[i][1] + bb[1],
                                       acc[i][2] + bb[2], acc[i][3] + bb[3]);
        ((float4*)op)[1] = make_float4(acc[i][4] + bb[4], acc[i][5] + bb[5],
                                       acc[i][6] + bb[6], acc[i][7] + bb[7]);
    }
}

// ---------------------------------------------------------------------------
extern "C" void kernel_launch(void* const* d_in, const int* in_sizes, int n_in,
                              void* d_out, int out_size) {
    const float* x     = (const float*)d_in[0];
    const float* theta = (const float*)d_in[1];
    const float* W     = (const float*)d_in[2];
    const float* bias  = (const float*)d_in[3];
    float* out = (float*)d_out;

    qattn_kernel<<<TOKENS / 4, 256>>>(x, theta);

    dim3 grid(EDIM / 128, TOKENS / 128);   // (4, 128)
    out_gemm_kernel<<<grid, 256>>>(W, bias, out);
}

// round 2
// speedup vs baseline: 3.2077x; 3.2077x over previous
#include <cuda_runtime.h>
#include <math_constants.h>

#define TOKENS (8 * 2048)
#define EDIM   512
#define NHEAD  64
#define DK     8

// Scratch: permuted attention output "mid" = (16384 rows x 512 cols) fp32 = 32 MB
__device__ float g_mid[(size_t)TOKENS * EDIM];

// ---- packed f32x2 helpers (Blackwell FFMA2 path) --------------------------
__device__ __forceinline__ unsigned long long pack2(float lo, float hi) {
    unsigned long long r;
    asm("mov.b64 %0, {%1, %2};" : "=l"(r) : "f"(lo), "f"(hi));
    return r;
}
__device__ __forceinline__ void unpack2(unsigned long long v, float& lo, float& hi) {
    asm("mov.b64 {%0, %1}, %2;" : "=f"(lo), "=f"(hi) : "l"(v));
}
__device__ __forceinline__ unsigned long long fma2(unsigned long long a,
                                                   unsigned long long b,
                                                   unsigned long long c) {
    unsigned long long d;
    asm("fma.rn.f32x2 %0, %1, %2, %3;" : "=l"(d) : "l"(a), "l"(b), "l"(c));
    return d;
}
__device__ __forceinline__ unsigned long long mul2(unsigned long long a,
                                                   unsigned long long b) {
    unsigned long long d;
    asm("mul.rn.f32x2 %0, %1, %2;" : "=l"(d) : "l"(a), "l"(b));
    return d;
}

// ---------------------------------------------------------------------------
// Kernel A: per-token quantum-projection attention, SINGLE PASS.
// No max-subtraction (|score| <= 2.83 so exp is safe), no s[64] state:
//   acc = sum_g exp(s_hg) * p_g ;  Z = sum_g exp(s_hg) ;  attn_h = acc / Z
// 256 threads = 4 tokens/CTA, 64 threads (one per head) per token.
// ---------------------------------------------------------------------------
__global__ __launch_bounds__(256, 4) void qattn_kernel(const float* __restrict__ x,
                                                       const float* __restrict__ theta) {
    __shared__ float sproj[4][EDIM];

    const int tl = threadIdx.x >> 6;   // token slot in CTA: 0..3
    const int h  = threadIdx.x & 63;   // head
    const int token = (blockIdx.x << 2) + tl;

    // theta (8 values, broadcast)
    float th[8];
    {
        const float4 t0 = ((const float4*)theta)[0];
        const float4 t1 = ((const float4*)theta)[1];
        th[0] = t0.x; th[1] = t0.y; th[2] = t0.z; th[3] = t0.w;
        th[4] = t1.x; th[5] = t1.y; th[6] = t1.z; th[7] = t1.w;
    }

    // proj[h, :] = cos(x + theta), kept packed as 4 f32x2 pairs
    unsigned long long p2[4];
    {
        const float4* xp = (const float4*)(x + (size_t)token * EDIM + h * DK);
        const float4 a0 = xp[0], a1 = xp[1];
        float p0 = __cosf(a0.x + th[0]), p1 = __cosf(a0.y + th[1]);
        float q0 = __cosf(a0.z + th[2]), q1 = __cosf(a0.w + th[3]);
        float r0 = __cosf(a1.x + th[4]), r1 = __cosf(a1.y + th[5]);
        float s0 = __cosf(a1.z + th[6]), s1 = __cosf(a1.w + th[7]);
        p2[0] = pack2(p0, p1); p2[1] = pack2(q0, q1);
        p2[2] = pack2(r0, r1); p2[3] = pack2(s0, s1);
        float4* sp = (float4*)&sproj[tl][h * DK];
        sp[0] = make_float4(p0, p1, q0, q1);
        sp[1] = make_float4(r0, r1, s0, s1);
    }
    __syncthreads();

    const float scale = 0.35355339059327373f;  // 1/sqrt(8)
    unsigned long long acc2[4];
    acc2[0] = acc2[1] = acc2[2] = acc2[3] = pack2(0.f, 0.f);
    float sum = 0.f;

    #pragma unroll 8
    for (int g = 0; g < NHEAD; g++) {
        const ulonglong2* qp = (const ulonglong2*)&sproj[tl][g * DK];
        const ulonglong2 qa = qp[0];   // floats 0..3 as two f32x2
        const ulonglong2 qb = qp[1];   // floats 4..7

        // dot(p, q) via packed FMA, horizontal add at the end
        unsigned long long d2 = mul2(p2[0], qa.x);
        d2 = fma2(p2[1], qa.y, d2);
        d2 = fma2(p2[2], qb.x, d2);
        d2 = fma2(p2[3], qb.y, d2);
        float dlo, dhi;
        unpack2(d2, dlo, dhi);

        const float e = __expf((dlo + dhi) * scale);
        sum += e;

        const unsigned long long e2 = pack2(e, e);
        acc2[0] = fma2(e2, qa.x, acc2[0]);
        acc2[1] = fma2(e2, qa.y, acc2[1]);
        acc2[2] = fma2(e2, qb.x, acc2[2]);
        acc2[3] = fma2(e2, qb.y, acc2[3]);
    }

    const float inv = 1.0f / sum;
    float a0, a1, a2, a3, a4, a5, a6, a7;
    unpack2(acc2[0], a0, a1); unpack2(acc2[1], a2, a3);
    unpack2(acc2[2], a4, a5); unpack2(acc2[3], a6, a7);

    // permuted store:  mid[b, h*32 + s/64, (s%64)*8 + d]
    const int b  = token >> 11;          // /2048
    const int sb = token & 2047;
    const size_t row = (size_t)(b * 2048) + (size_t)(h * 32) + (size_t)(sb >> 6);
    float* op = g_mid + row * EDIM + (size_t)((sb & 63) * DK);
    ((float4*)op)[0] = make_float4(a0 * inv, a1 * inv, a2 * inv, a3 * inv);
    ((float4*)op)[1] = make_float4(a4 * inv, a5 * inv, a6 * inv, a7 * inv);
}

// ---------------------------------------------------------------------------
// Kernel B: out[16384,512] = mid @ W^T + bias   (W is [512 out, 512 in])
// 128x128x8 SGEMM, 256 threads, 8x8 microtile computed as 8x4 f32x2 pairs.
// A tile stored DUPLICATED (v,v) as uint64 in smem so the inner loop needs
// no dup-movs: acc2[i][j2] = fma2(a_dup[i], b_pair[j2], acc2[i][j2]).
// ---------------------------------------------------------------------------
__global__ __launch_bounds__(256, 2) void out_gemm_kernel(const float* __restrict__ W,
                                                          const float* __restrict__ bias,
                                                          float* __restrict__ out) {
    __shared__ unsigned long long As2[8][130];   // duplicated A, +2 pad
    __shared__ float Bs[8][132];                 // +4 pad

    const int tid = threadIdx.x;
    const int rowBase = blockIdx.y * 128;   // over 16384 rows of mid
    const int colBase = blockIdx.x * 128;   // over 512 output cols

    const int lr = tid >> 1;          // 0..127 : row within tile
    const int lk = (tid & 1) * 4;     // 0 or 4 : k offset

    const float* Aptr = g_mid + (size_t)(rowBase + lr) * EDIM + lk;
    const float* Bptr = W     + (size_t)(colBase + lr) * EDIM + lk;

    const int tx = tid & 15;   // col group (8 cols = 4 pairs)
    const int ty = tid >> 4;   // row group (8 rows)

    unsigned long long acc2[8][4];
    #pragma unroll
    for (int i = 0; i < 8; i++)
        #pragma unroll
        for (int j = 0; j < 4; j++) acc2[i][j] = pack2(0.f, 0.f);

    for (int k0 = 0; k0 < EDIM; k0 += 8) {
        const float4 av = *(const float4*)(Aptr + k0);
        const float4 bv = *(const float4*)(Bptr + k0);
        __syncthreads();   // previous iteration's reads done before overwrite
        As2[lk + 0][lr] = pack2(av.x, av.x);
        As2[lk + 1][lr] = pack2(av.y, av.y);
        As2[lk + 2][lr] = pack2(av.z, av.z);
        As2[lk + 3][lr] = pack2(av.w, av.w);
        Bs[lk + 0][lr] = bv.x; Bs[lk + 1][lr] = bv.y;
        Bs[lk + 2][lr] = bv.z; Bs[lk + 3][lr] = bv.w;
        __syncthreads();

        #pragma unroll
        for (int kk = 0; kk < 8; kk++) {
            const ulonglong2 a01 = *(const ulonglong2*)&As2[kk][ty * 8 + 0];
            const ulonglong2 a23 = *(const ulonglong2*)&As2[kk][ty * 8 + 2];
            const ulonglong2 a45 = *(const ulonglong2*)&As2[kk][ty * 8 + 4];
            const ulonglong2 a67 = *(const ulonglong2*)&As2[kk][ty * 8 + 6];
            const ulonglong2 b03 = *(const ulonglong2*)&Bs[kk][tx * 8 + 0];
            const ulonglong2 b47 = *(const ulonglong2*)&Bs[kk][tx * 8 + 4];

            acc2[0][0] = fma2(a01.x, b03.x, acc2[0][0]);
            acc2[0][1] = fma2(a01.x, b03.y, acc2[0][1]);
            acc2[0][2] = fma2(a01.x, b47.x, acc2[0][2]);
            acc2[0][3] = fma2(a01.x, b47.y, acc2[0][3]);

            acc2[1][0] = fma2(a01.y, b03.x, acc2[1][0]);
            acc2[1][1] = fma2(a01.y, b03.y, acc2[1][1]);
            acc2[1][2] = fma2(a01.y, b47.x, acc2[1][2]);
            acc2[1][3] = fma2(a01.y, b47.y, acc2[1][3]);

            acc2[2][0] = fma2(a23.x, b03.x, acc2[2][0]);
            acc2[2][1] = fma2(a23.x, b03.y, acc2[2][1]);
            acc2[2][2] = fma2(a23.x, b47.x, acc2[2][2]);
            acc2[2][3] = fma2(a23.x, b47.y, acc2[2][3]);

            acc2[3][0] = fma2(a23.y, b03.x, acc2[3][0]);
            acc2[3][1] = fma2(a23.y, b03.y, acc2[3][1]);
            acc2[3][2] = fma2(a23.y, b47.x, acc2[3][2]);
            acc2[3][3] = fma2(a23.y, b47.y, acc2[3][3]);

            acc2[4][0] = fma2(a45.x, b03.x, acc2[4][0]);
            acc2[4][1] = fma2(a45.x, b03.y, acc2[4][1]);
            acc2[4][2] = fma2(a45.x, b47.x, acc2[4][2]);
            acc2[4][3] = fma2(a45.x, b47.y, acc2[4][3]);

            acc2[5][0] = fma2(a45.y, b03.x, acc2[5][0]);
            acc2[5][1] = fma2(a45.y, b03.y, acc2[5][1]);
            acc2[5][2] = fma2(a45.y, b47.x, acc2[5][2]);
            acc2[5][3] = fma2(a45.y, b47.y, acc2[5][3]);

            acc2[6][0] = fma2(a67.x, b03.x, acc2[6][0]);
            acc2[6][1] = fma2(a67.x, b03.y, acc2[6][1]);
            acc2[6][2] = fma2(a67.x, b47.x, acc2[6][2]);
            acc2[6][3] = fma2(a67.x, b47.y, acc2[6][3]);

            acc2[7][0] = fma2(a67.y, b03.x, acc2[7][0]);
            acc2[7][1] = fma2(a67.y, b03.y, acc2[7][1]);
            acc2[7][2] = fma2(a67.y, b47.x, acc2[7][2]);
            acc2[7][3] = fma2(a67.y, b47.y, acc2[7][3]);
        }
    }

    // epilogue: + bias, write out
    float bb[8];
    *(float4*)(bb)     = *(const float4*)&bias[colBase + tx * 8];
    *(float4*)(bb + 4) = *(const float4*)&bias[colBase + tx * 8 + 4];

    #pragma unroll
    for (int i = 0; i < 8; i++) {
        float c[8];
        #pragma unroll
        for (int j = 0; j < 4; j++) unpack2(acc2[i][j], c[2 * j], c[2 * j + 1]);
        const size_t r = (size_t)(rowBase + ty * 8 + i);
        float* op = out + r * EDIM + colBase + tx * 8;
        ((float4*)op)[0] = make_float4(c[0] + bb[0], c[1] + bb[1],
                                       c[2] + bb[2], c[3] + bb[3]);
        ((float4*)op)[1] = make_float4(c[4] + bb[4], c[5] + bb[5],
                                       c[6] + bb[6], c[7] + bb[7]);
    }
}

// ---------------------------------------------------------------------------
extern "C" void kernel_launch(void* const* d_in, const int* in_sizes, int n_in,
                              void* d_out, int out_size) {
    const float* x     = (const float*)d_in[0];
    const float* theta = (const float*)d_in[1];
    const float* W     = (const float*)d_in[2];
    const float* bias  = (const float*)d_in[3];
    float* out = (float*)d_out;

    qattn_kernel<<<TOKENS / 4, 256>>>(x, theta);

    dim3 grid(EDIM / 128, TOKENS / 128);   // (4, 128)
    out_gemm_kernel<<<grid, 256>>>(W, bias, out);
}

// round 4
// speedup vs baseline: 7.0611x; 2.2013x over previous
#include <cuda_runtime.h>
#include <cuda_bf16.h>
#include <math_constants.h>

#define TOKENS (8 * 2048)
#define EDIM   512
#define NHEAD  64
#define DK     8

// Split-bf16 operands:  value = hi + lo  (each bf16, stored as ushort)
__device__ unsigned short g_Ah[(size_t)TOKENS * EDIM];
__device__ unsigned short g_Al[(size_t)TOKENS * EDIM];
__device__ unsigned short g_Bh[(size_t)EDIM * EDIM];
__device__ unsigned short g_Bl[(size_t)EDIM * EDIM];

// ---- packed f32x2 helpers (qattn) ----------------------------------------
__device__ __forceinline__ unsigned long long pack2(float lo, float hi) {
    unsigned long long r;
    asm("mov.b64 %0, {%1, %2};" : "=l"(r) : "f"(lo), "f"(hi));
    return r;
}
__device__ __forceinline__ void unpack2(unsigned long long v, float& lo, float& hi) {
    asm("mov.b64 {%0, %1}, %2;" : "=f"(lo), "=f"(hi) : "l"(v));
}
__device__ __forceinline__ unsigned long long fma2(unsigned long long a,
                                                   unsigned long long b,
                                                   unsigned long long c) {
    unsigned long long d;
    asm("fma.rn.f32x2 %0, %1, %2, %3;" : "=l"(d) : "l"(a), "l"(b), "l"(c));
    return d;
}
__device__ __forceinline__ unsigned long long mul2(unsigned long long a,
                                                   unsigned long long b) {
    unsigned long long d;
    asm("mul.rn.f32x2 %0, %1, %2;" : "=l"(d) : "l"(a), "l"(b));
    return d;
}

// ---- bf16 split helper ----------------------------------------------------
__device__ __forceinline__ void bsplit(float v, unsigned short& h, unsigned short& l) {
    __nv_bfloat16 hb = __float2bfloat16(v);
    h = __bfloat16_as_ushort(hb);
    l = __bfloat16_as_ushort(__float2bfloat16(v - __bfloat162float(hb)));
}

// ---- smem / async / mma helpers ------------------------------------------
__device__ __forceinline__ unsigned smem_u32(const void* p) {
    unsigned a;
    asm("{ .reg .u64 t; cvta.to.shared.u64 t, %1; cvt.u32.u64 %0, t; }" : "=r"(a) : "l"(p));
    return a;
}
__device__ __forceinline__ void cp16(unsigned dst, const void* src) {
    asm volatile("cp.async.cg.shared.global [%0], [%1], 16;" :: "r"(dst), "l"(src));
}
__device__ __forceinline__ void ldsm_x4(unsigned& r0, unsigned& r1, unsigned& r2,
                                        unsigned& r3, unsigned addr) {
    asm volatile("ldmatrix.sync.aligned.m8n8.x4.shared.b16 {%0,%1,%2,%3}, [%4];"
                 : "=r"(r0), "=r"(r1), "=r"(r2), "=r"(r3) : "r"(addr));
}
__device__ __forceinline__ void mma_bf16(float* c, const unsigned* a,
                                         unsigned b0, unsigned b1) {
    asm volatile("mma.sync.aligned.m16n8k16.row.col.f32.bf16.bf16.f32 "
                 "{%0,%1,%2,%3}, {%4,%5,%6,%7}, {%8,%9}, {%0,%1,%2,%3};"
                 : "+f"(c[0]), "+f"(c[1]), "+f"(c[2]), "+f"(c[3])
                 : "r"(a[0]), "r"(a[1]), "r"(a[2]), "r"(a[3]), "r"(b0), "r"(b1));
}

#define SWZ(o) ((o) ^ (((o) >> 3) & 0x70))

// ---------------------------------------------------------------------------
// Kernel A: per-token quantum attention, single pass; writes split-bf16 mid.
// ---------------------------------------------------------------------------
__global__ __launch_bounds__(256, 4) void qattn_kernel(const float* __restrict__ x,
                                                       const float* __restrict__ theta) {
    __shared__ float sproj[4][EDIM];

    const int tl = threadIdx.x >> 6;
    const int h  = threadIdx.x & 63;
    const int token = (blockIdx.x << 2) + tl;

    float th[8];
    {
        const float4 t0 = ((const float4*)theta)[0];
        const float4 t1 = ((const float4*)theta)[1];
        th[0] = t0.x; th[1] = t0.y; th[2] = t0.z; th[3] = t0.w;
        th[4] = t1.x; th[5] = t1.y; th[6] = t1.z; th[7] = t1.w;
    }

    unsigned long long p2[4];
    {
        const float4* xp = (const float4*)(x + (size_t)token * EDIM + h * DK);
        const float4 a0 = xp[0], a1 = xp[1];
        float p0 = __cosf(a0.x + th[0]), p1 = __cosf(a0.y + th[1]);
        float q0 = __cosf(a0.z + th[2]), q1 = __cosf(a0.w + th[3]);
        float r0 = __cosf(a1.x + th[4]), r1 = __cosf(a1.y + th[5]);
        float s0 = __cosf(a1.z + th[6]), s1 = __cosf(a1.w + th[7]);
        p2[0] = pack2(p0, p1); p2[1] = pack2(q0, q1);
        p2[2] = pack2(r0, r1); p2[3] = pack2(s0, s1);
        float4* sp = (float4*)&sproj[tl][h * DK];
        sp[0] = make_float4(p0, p1, q0, q1);
        sp[1] = make_float4(r0, r1, s0, s1);
    }
    __syncthreads();

    const float scale = 0.35355339059327373f;
    unsigned long long acc2[4];
    acc2[0] = acc2[1] = acc2[2] = acc2[3] = pack2(0.f, 0.f);
    float sum = 0.f;

    #pragma unroll 8
    for (int g = 0; g < NHEAD; g++) {
        const ulonglong2* qp = (const ulonglong2*)&sproj[tl][g * DK];
        const ulonglong2 qa = qp[0];
        const ulonglong2 qb = qp[1];

        unsigned long long d2 = mul2(p2[0], qa.x);
        d2 = fma2(p2[1], qa.y, d2);
        d2 = fma2(p2[2], qb.x, d2);
        d2 = fma2(p2[3], qb.y, d2);
        float dlo, dhi;
        unpack2(d2, dlo, dhi);

        const float e = __expf((dlo + dhi) * scale);
        sum += e;

        const unsigned long long e2 = pack2(e, e);
        acc2[0] = fma2(e2, qa.x, acc2[0]);
        acc2[1] = fma2(e2, qa.y, acc2[1]);
        acc2[2] = fma2(e2, qb.x, acc2[2]);
        acc2[3] = fma2(e2, qb.y, acc2[3]);
    }

    const float inv = 1.0f / sum;
    float v[8];
    unpack2(acc2[0], v[0], v[1]); unpack2(acc2[1], v[2], v[3]);
    unpack2(acc2[2], v[4], v[5]); unpack2(acc2[3], v[6], v[7]);

    unsigned short hs[8], ls[8];
    #pragma unroll
    for (int i = 0; i < 8; i++) bsplit(v[i] * inv, hs[i], ls[i]);

    // permuted store:  mid[b, h*32 + s/64, (s%64)*8 + d]
    const int b  = token >> 11;
    const int sb = token & 2047;
    const size_t row = (size_t)(b * 2048) + (size_t)(h * 32) + (size_t)(sb >> 6);
    const size_t off = row * EDIM + (size_t)((sb & 63) * DK);

    uint4 hu, lu;
    hu.x = (unsigned)hs[0] | ((unsigned)hs[1] << 16);
    hu.y = (unsigned)hs[2] | ((unsigned)hs[3] << 16);
    hu.z = (unsigned)hs[4] | ((unsigned)hs[5] << 16);
    hu.w = (unsigned)hs[6] | ((unsigned)hs[7] << 16);
    lu.x = (unsigned)ls[0] | ((unsigned)ls[1] << 16);
    lu.y = (unsigned)ls[2] | ((unsigned)ls[3] << 16);
    lu.z = (unsigned)ls[4] | ((unsigned)ls[5] << 16);
    lu.w = (unsigned)ls[6] | ((unsigned)ls[7] << 16);
    *(uint4*)(g_Ah + off) = hu;
    *(uint4*)(g_Al + off) = lu;
}

// ---------------------------------------------------------------------------
// Kernel P: split W into hi/lo bf16.
// ---------------------------------------------------------------------------
__global__ __launch_bounds__(256) void wsplit_kernel(const float* __restrict__ W) {
    const int idx = blockIdx.x * blockDim.x + threadIdx.x;  // 0..65535
    const float4 w = ((const float4*)W)[idx];
    unsigned short h0, h1, h2, h3, l0, l1, l2, l3;
    bsplit(w.x, h0, l0); bsplit(w.y, h1, l1);
    bsplit(w.z, h2, l2); bsplit(w.w, h3, l3);
    uint2 hu, lu;
    hu.x = (unsigned)h0 | ((unsigned)h1 << 16);
    hu.y = (unsigned)h2 | ((unsigned)h3 << 16);
    lu.x = (unsigned)l0 | ((unsigned)l1 << 16);
    lu.y = (unsigned)l2 | ((unsigned)l3 << 16);
    ((uint2*)g_Bh)[idx] = hu;
    ((uint2*)g_Bl)[idx] = lu;
}

// ---------------------------------------------------------------------------
// Kernel B: split-bf16 GEMM on mma.sync (m16n8k16).
// out[16384,512] = (Ah+Al)(Bh+Bl)^T + bias ~= AhBh + AhBl + AlBh
// CTA 128x128, K-chunks of 64; 8 warps in 4(m) x 2(n); warp tile 32x64.
// smem: 4 x 16KB SW128 tiles (Ah, Al, Bh, Bl).
// ---------------------------------------------------------------------------
#define AH_OFF 0
#define AL_OFF 16384
#define BH_OFF 32768
#define BL_OFF 49152
#define GSMEM_BYTES 65536

__global__ __launch_bounds__(256) void out_gemm_mma(const float* __restrict__ bias,
                                                    float* __restrict__ out) {
    extern __shared__ char smem[];
    const unsigned sb = smem_u32(smem);
    const int tid = threadIdx.x;
    const int wid = tid >> 5;
    const int lid = tid & 31;

    const int rowBase = blockIdx.y * 128;
    const int colBase = blockIdx.x * 128;

    const int wy = wid & 3;    // m: 32 rows each
    const int wx = wid >> 2;   // n: 64 cols each

    // ldmatrix lane decomposition
    const int lr  = lid & 7;
    const int sub = lid >> 3;

    float acc[2][8][4];
    #pragma unroll
    for (int mt = 0; mt < 2; mt++)
        #pragma unroll
        for (int nt = 0; nt < 8; nt++)
            #pragma unroll
            for (int q = 0; q < 4; q++) acc[mt][nt][q] = 0.f;

    for (int c = 0; c < 8; c++) {
        // fill 4 tiles: 4096 16B vectors, 16 per thread
        #pragma unroll
        for (int i = 0; i < 16; i++) {
            const int v    = i * 256 + tid;
            const int tile = v >> 10;
            const int rem  = v & 1023;
            const int r    = rem >> 3;
            const int c16  = rem & 7;
            const unsigned short* src;
            if      (tile == 0) src = g_Ah + (size_t)(rowBase + r) * EDIM;
            else if (tile == 1) src = g_Al + (size_t)(rowBase + r) * EDIM;
            else if (tile == 2) src = g_Bh + (size_t)(colBase + r) * EDIM;
            else                src = g_Bl + (size_t)(colBase + r) * EDIM;
            src += c * 64 + c16 * 8;
            const unsigned dst = sb + tile * 16384 + SWZ(r * 128 + c16 * 16);
            cp16(dst, src);
        }
        asm volatile("cp.async.commit_group;" ::: "memory");
        asm volatile("cp.async.wait_group 0;" ::: "memory");
        __syncthreads();

        #pragma unroll
        for (int kk = 0; kk < 4; kk++) {
            const int kb = kk * 32;   // bytes: 16 bf16 per k16 step

            // A fragments (hi & lo) for this warp's 32 rows
            unsigned ah[2][4], al[2][4];
            #pragma unroll
            for (int mt = 0; mt < 2; mt++) {
                const int rowA = wy * 32 + mt * 16 + lr + (sub & 1) * 8;
                const int colb = kb + (sub >> 1) * 16;
                const unsigned off = SWZ(rowA * 128 + colb);
                ldsm_x4(ah[mt][0], ah[mt][1], ah[mt][2], ah[mt][3], sb + AH_OFF + off);
                ldsm_x4(al[mt][0], al[mt][1], al[mt][2], al[mt][3], sb + AL_OFF + off);
            }

            #pragma unroll
            for (int nt16 = 0; nt16 < 4; nt16++) {
                const int rowB = wx * 64 + nt16 * 16 + lr + (sub >> 1) * 8;
                const int colb = kb + (sub & 1) * 16;
                const unsigned off = SWZ(rowB * 128 + colb);
                unsigned bh[4], bl[4];
                ldsm_x4(bh[0], bh[1], bh[2], bh[3], sb + BH_OFF + off);
                ldsm_x4(bl[0], bl[1], bl[2], bl[3], sb + BL_OFF + off);

                #pragma unroll
                for (int mt = 0; mt < 2; mt++) {
                    float* c0 = acc[mt][nt16 * 2];
                    float* c1 = acc[mt][nt16 * 2 + 1];
                    mma_bf16(c0, ah[mt], bh[0], bh[1]);
                    mma_bf16(c0, ah[mt], bl[0], bl[1]);
                    mma_bf16(c0, al[mt], bh[0], bh[1]);
                    mma_bf16(c1, ah[mt], bh[2], bh[3]);
                    mma_bf16(c1, ah[mt], bl[2], bl[3]);
                    mma_bf16(c1, al[mt], bh[2], bh[3]);
                }
            }
        }
        __syncthreads();
    }

    // epilogue: bias + store (thread t of quad owns cols 2*(t%4), rows t/4 & +8)
    const int qrow = lid >> 2;
    const int qcol = (lid & 3) * 2;
    #pragma unroll
    for (int mt = 0; mt < 2; mt++) {
        #pragma unroll
        for (int nt = 0; nt < 8; nt++) {
            const int row = rowBase + wy * 32 + mt * 16 + qrow;
            const int col = colBase + wx * 64 + nt * 8 + qcol;
            const float2 bv = *(const float2*)&bias[col];
            float* o0 = out + (size_t)row * EDIM + col;
            float* o1 = o0 + 8 * EDIM;
            *(float2*)o0 = make_float2(acc[mt][nt][0] + bv.x, acc[mt][nt][1] + bv.y);
            *(float2*)o1 = make_float2(acc[mt][nt][2] + bv.x, acc[mt][nt][3] + bv.y);
        }
    }
}

// ---------------------------------------------------------------------------
extern "C" void kernel_launch(void* const* d_in, const int* in_sizes, int n_in,
                              void* d_out, int out_size) {
    const float* x     = (const float*)d_in[0];
    const float* theta = (const float*)d_in[1];
    const float* W     = (const float*)d_in[2];
    const float* bias  = (const float*)d_in[3];
    float* out = (float*)d_out;

    cudaFuncSetAttribute(out_gemm_mma, cudaFuncAttributeMaxDynamicSharedMemorySize,
                         GSMEM_BYTES);

    wsplit_kernel<<<256, 256>>>(W);
    qattn_kernel<<<TOKENS / 4, 256>>>(x, theta);

    dim3 grid(EDIM / 128, TOKENS / 128);   // (4, 128)
    out_gemm_mma<<<grid, 256, GSMEM_BYTES>>>(bias, out);
}

// round 5
// speedup vs baseline: 8.3504x; 1.1826x over previous
#include <cuda_runtime.h>
#include <cuda_bf16.h>
#include <math_constants.h>

#define TOKENS (8 * 2048)
#define EDIM   512
#define NHEAD  64
#define DK     8

// Split-bf16 operands:  value = hi + lo  (each bf16, stored as ushort)
__device__ unsigned short g_Ah[(size_t)TOKENS * EDIM];
__device__ unsigned short g_Al[(size_t)TOKENS * EDIM];
__device__ unsigned short g_Bh[(size_t)EDIM * EDIM];
__device__ unsigned short g_Bl[(size_t)EDIM * EDIM];

// ---- packed f32x2 helpers (qattn) ----------------------------------------
__device__ __forceinline__ unsigned long long pack2(float lo, float hi) {
    unsigned long long r;
    asm("mov.b64 %0, {%1, %2};" : "=l"(r) : "f"(lo), "f"(hi));
    return r;
}
__device__ __forceinline__ void unpack2(unsigned long long v, float& lo, float& hi) {
    asm("mov.b64 {%0, %1}, %2;" : "=f"(lo), "=f"(hi) : "l"(v));
}
__device__ __forceinline__ unsigned long long fma2(unsigned long long a,
                                                   unsigned long long b,
                                                   unsigned long long c) {
    unsigned long long d;
    asm("fma.rn.f32x2 %0, %1, %2, %3;" : "=l"(d) : "l"(a), "l"(b), "l"(c));
    return d;
}
__device__ __forceinline__ unsigned long long mul2(unsigned long long a,
                                                   unsigned long long b) {
    unsigned long long d;
    asm("mul.rn.f32x2 %0, %1, %2;" : "=l"(d) : "l"(a), "l"(b));
    return d;
}
__device__ __forceinline__ float ex2(float x) {
    float y;
    asm("ex2.approx.f32 %0, %1;" : "=f"(y) : "f"(x));
    return y;
}

// ---- bf16 split helper ----------------------------------------------------
__device__ __forceinline__ void bsplit(float v, unsigned short& h, unsigned short& l) {
    __nv_bfloat16 hb = __float2bfloat16(v);
    h = __bfloat16_as_ushort(hb);
    l = __bfloat16_as_ushort(__float2bfloat16(v - __bfloat162float(hb)));
}

// ---- smem / async / mma helpers ------------------------------------------
__device__ __forceinline__ unsigned smem_u32(const void* p) {
    unsigned a;
    asm("{ .reg .u64 t; cvta.to.shared.u64 t, %1; cvt.u32.u64 %0, t; }" : "=r"(a) : "l"(p));
    return a;
}
__device__ __forceinline__ void cp16(unsigned dst, const void* src) {
    asm volatile("cp.async.cg.shared.global [%0], [%1], 16;" :: "r"(dst), "l"(src));
}
__device__ __forceinline__ void ldsm_x4(unsigned& r0, unsigned& r1, unsigned& r2,
                                        unsigned& r3, unsigned addr) {
    asm volatile("ldmatrix.sync.aligned.m8n8.x4.shared.b16 {%0,%1,%2,%3}, [%4];"
                 : "=r"(r0), "=r"(r1), "=r"(r2), "=r"(r3) : "r"(addr));
}
__device__ __forceinline__ void mma_bf16(float* c, const unsigned* a,
                                         unsigned b0, unsigned b1) {
    asm volatile("mma.sync.aligned.m16n8k16.row.col.f32.bf16.bf16.f32 "
                 "{%0,%1,%2,%3}, {%4,%5,%6,%7}, {%8,%9}, {%0,%1,%2,%3};"
                 : "+f"(c[0]), "+f"(c[1]), "+f"(c[2]), "+f"(c[3])
                 : "r"(a[0]), "r"(a[1]), "r"(a[2]), "r"(a[3]), "r"(b0), "r"(b1));
}

#define SWZ64(o) ((o) ^ (((o) >> 3) & 0x30))

// ---------------------------------------------------------------------------
// Kernel A: quantum attention (single pass) + folded W-split (blocks 0..255).
// ---------------------------------------------------------------------------
__global__ __launch_bounds__(256, 4) void qattn_kernel(const float* __restrict__ x,
                                                       const float* __restrict__ theta,
                                                       const float* __restrict__ W) {
    __shared__ float sproj[4][EDIM];

    // Folded W split: blocks 0..255 each handle 256 float4s (one per thread).
    if (blockIdx.x < 256) {
        const int idx = blockIdx.x * 256 + threadIdx.x;  // 0..65535
        const float4 w = ((const float4*)W)[idx];
        unsigned short h0, h1, h2, h3, l0, l1, l2, l3;
        bsplit(w.x, h0, l0); bsplit(w.y, h1, l1);
        bsplit(w.z, h2, l2); bsplit(w.w, h3, l3);
        uint2 hu, lu;
        hu.x = (unsigned)h0 | ((unsigned)h1 << 16);
        hu.y = (unsigned)h2 | ((unsigned)h3 << 16);
        lu.x = (unsigned)l0 | ((unsigned)l1 << 16);
        lu.y = (unsigned)l2 | ((unsigned)l3 << 16);
        ((uint2*)g_Bh)[idx] = hu;
        ((uint2*)g_Bl)[idx] = lu;
    }

    const int tl = threadIdx.x >> 6;
    const int h  = threadIdx.x & 63;
    const int token = (blockIdx.x << 2) + tl;

    float th[8];
    {
        const float4 t0 = ((const float4*)theta)[0];
        const float4 t1 = ((const float4*)theta)[1];
        th[0] = t0.x; th[1] = t0.y; th[2] = t0.z; th[3] = t0.w;
        th[4] = t1.x; th[5] = t1.y; th[6] = t1.z; th[7] = t1.w;
    }

    // dot-operand copy pre-scaled by (1/sqrt(8)) * log2(e) so the softmax
    // exp becomes a single ex2.approx on the raw horizontal sum.
    const float SL = 0.35355339059327373f * 1.4426950408889634f;
    unsigned long long p2[4];
    {
        const float4* xp = (const float4*)(x + (size_t)token * EDIM + h * DK);
        const float4 a0 = xp[0], a1 = xp[1];
        float p0 = __cosf(a0.x + th[0]), p1 = __cosf(a0.y + th[1]);
        float q0 = __cosf(a0.z + th[2]), q1 = __cosf(a0.w + th[3]);
        float r0 = __cosf(a1.x + th[4]), r1 = __cosf(a1.y + th[5]);
        float s0 = __cosf(a1.z + th[6]), s1 = __cosf(a1.w + th[7]);
        p2[0] = pack2(p0 * SL, p1 * SL); p2[1] = pack2(q0 * SL, q1 * SL);
        p2[2] = pack2(r0 * SL, r1 * SL); p2[3] = pack2(s0 * SL, s1 * SL);
        float4* sp = (float4*)&sproj[tl][h * DK];
        sp[0] = make_float4(p0, p1, q0, q1);
        sp[1] = make_float4(r0, r1, s0, s1);
    }
    __syncthreads();

    unsigned long long acc2[4];
    acc2[0] = acc2[1] = acc2[2] = acc2[3] = pack2(0.f, 0.f);
    float sum = 0.f;

    #pragma unroll 8
    for (int g = 0; g < NHEAD; g++) {
        const ulonglong2* qp = (const ulonglong2*)&sproj[tl][g * DK];
        const ulonglong2 qa = qp[0];
        const ulonglong2 qb = qp[1];

        unsigned long long d2 = mul2(p2[0], qa.x);
        d2 = fma2(p2[1], qa.y, d2);
        d2 = fma2(p2[2], qb.x, d2);
        d2 = fma2(p2[3], qb.y, d2);
        float dlo, dhi;
        unpack2(d2, dlo, dhi);

        const float e = ex2(dlo + dhi);   // = exp(score/sqrt(8))
        sum += e;

        const unsigned long long e2 = pack2(e, e);
        acc2[0] = fma2(e2, qa.x, acc2[0]);
        acc2[1] = fma2(e2, qa.y, acc2[1]);
        acc2[2] = fma2(e2, qb.x, acc2[2]);
        acc2[3] = fma2(e2, qb.y, acc2[3]);
    }

    const float inv = 1.0f / sum;
    float v[8];
    unpack2(acc2[0], v[0], v[1]); unpack2(acc2[1], v[2], v[3]);
    unpack2(acc2[2], v[4], v[5]); unpack2(acc2[3], v[6], v[7]);

    unsigned short hs[8], ls[8];
    #pragma unroll
    for (int i = 0; i < 8; i++) bsplit(v[i] * inv, hs[i], ls[i]);

    // permuted store:  mid[b, h*32 + s/64, (s%64)*8 + d]
    const int b  = token >> 11;
    const int sb = token & 2047;
    const size_t row = (size_t)(b * 2048) + (size_t)(h * 32) + (size_t)(sb >> 6);
    const size_t off = row * EDIM + (size_t)((sb & 63) * DK);

    uint4 hu, lu;
    hu.x = (unsigned)hs[0] | ((unsigned)hs[1] << 16);
    hu.y = (unsigned)hs[2] | ((unsigned)hs[3] << 16);
    hu.z = (unsigned)hs[4] | ((unsigned)hs[5] << 16);
    hu.w = (unsigned)hs[6] | ((unsigned)hs[7] << 16);
    lu.x = (unsigned)ls[0] | ((unsigned)ls[1] << 16);
    lu.y = (unsigned)ls[2] | ((unsigned)ls[3] << 16);
    lu.z = (unsigned)ls[4] | ((unsigned)ls[5] << 16);
    lu.w = (unsigned)ls[6] | ((unsigned)ls[7] << 16);
    *(uint4*)(g_Ah + off) = hu;
    *(uint4*)(g_Al + off) = lu;
}

// ---------------------------------------------------------------------------
// Kernel B: split-bf16 GEMM on mma.sync, 2-stage cp.async pipeline.
// out[16384,512] = (Ah+Al)(Bh+Bl)^T + bias ~= AhBh + AhBl + AlBh
// CTA 128x128, K-chunks of 32 (SW64-swizzled 8KB tiles), 2 stages = 64KB.
// 8 warps in 4(m) x 2(n); warp tile 32x64.
// ---------------------------------------------------------------------------
#define TILE_B  8192
#define STAGE_B 32768
#define GSMEM_BYTES (2 * STAGE_B)
#define AH_T 0
#define AL_T 1
#define BH_T 2
#define BL_T 3

__device__ __forceinline__ void load_chunk(unsigned sb, int stage, int c,
                                           int rowBase, int colBase, int tid) {
    const unsigned base = sb + stage * STAGE_B;
    #pragma unroll
    for (int i = 0; i < 8; i++) {
        const int v    = i * 256 + tid;   // 0..2047
        const int tile = v >> 9;          // 512 v16 per tile
        const int rem  = v & 511;
        const int r    = rem >> 2;
        const int c16  = rem & 3;
        const unsigned short* src;
        if      (tile == 0) src = g_Ah + (size_t)(rowBase + r) * EDIM;
        else if (tile == 1) src = g_Al + (size_t)(rowBase + r) * EDIM;
        else if (tile == 2) src = g_Bh + (size_t)(colBase + r) * EDIM;
        else                src = g_Bl + (size_t)(colBase + r) * EDIM;
        src += c * 32 + c16 * 8;
        cp16(base + tile * TILE_B + SWZ64(r * 64 + c16 * 16), src);
    }
    asm volatile("cp.async.commit_group;" ::: "memory");
}

__global__ __launch_bounds__(256, 2) void out_gemm_mma(const float* __restrict__ bias,
                                                       float* __restrict__ out) {
    extern __shared__ char smem[];
    const unsigned sb = smem_u32(smem);
    const int tid = threadIdx.x;
    const int wid = tid >> 5;
    const int lid = tid & 31;

    const int rowBase = blockIdx.y * 128;
    const int colBase = blockIdx.x * 128;

    const int wy = wid & 3;    // m: 32 rows each
    const int wx = wid >> 2;   // n: 64 cols each

    const int lr  = lid & 7;
    const int sub = lid >> 3;

    float acc[2][8][4];
    #pragma unroll
    for (int mt = 0; mt < 2; mt++)
        #pragma unroll
        for (int nt = 0; nt < 8; nt++)
            #pragma unroll
            for (int q = 0; q < 4; q++) acc[mt][nt][q] = 0.f;

    load_chunk(sb, 0, 0, rowBase, colBase, tid);

    for (int c = 0; c < 16; c++) {
        if (c + 1 < 16) {
            load_chunk(sb, (c + 1) & 1, c + 1, rowBase, colBase, tid);
            asm volatile("cp.async.wait_group 1;" ::: "memory");
        } else {
            asm volatile("cp.async.wait_group 0;" ::: "memory");
        }
        __syncthreads();

        const unsigned stg = sb + (unsigned)(c & 1) * STAGE_B;

        #pragma unroll
        for (int kk = 0; kk < 2; kk++) {
            const int kb = kk * 32;   // 16 bf16 per k16 step

            unsigned ah[2][4], al[2][4];
            #pragma unroll
            for (int mt = 0; mt < 2; mt++) {
                const int rowA = wy * 32 + mt * 16 + lr + (sub & 1) * 8;
                const int colb = kb + (sub >> 1) * 16;
                const unsigned off = SWZ64(rowA * 64 + colb);
                ldsm_x4(ah[mt][0], ah[mt][1], ah[mt][2], ah[mt][3], stg + AH_T * TILE_B + off);
                ldsm_x4(al[mt][0], al[mt][1], al[mt][2], al[mt][3], stg + AL_T * TILE_B + off);
            }

            #pragma unroll
            for (int nt16 = 0; nt16 < 4; nt16++) {
                const int rowB = wx * 64 + nt16 * 16 + lr + (sub >> 1) * 8;
                const int colb = kb + (sub & 1) * 16;
                const unsigned off = SWZ64(rowB * 64 + colb);
                unsigned bh[4], bl[4];
                ldsm_x4(bh[0], bh[1], bh[2], bh[3], stg + BH_T * TILE_B + off);
                ldsm_x4(bl[0], bl[1], bl[2], bl[3], stg + BL_T * TILE_B + off);

                #pragma unroll
                for (int mt = 0; mt < 2; mt++) {
                    float* c0 = acc[mt][nt16 * 2];
                    float* c1 = acc[mt][nt16 * 2 + 1];
                    mma_bf16(c0, ah[mt], bh[0], bh[1]);
                    mma_bf16(c0, ah[mt], bl[0], bl[1]);
                    mma_bf16(c0, al[mt], bh[0], bh[1]);
                    mma_bf16(c1, ah[mt], bh[2], bh[3]);
                    mma_bf16(c1, ah[mt], bl[2], bl[3]);
                    mma_bf16(c1, al[mt], bh[2], bh[3]);
                }
            }
        }
        __syncthreads();
    }

    // epilogue: bias + store
    const int qrow = lid >> 2;
    const int qcol = (lid & 3) * 2;
    #pragma unroll
    for (int mt = 0; mt < 2; mt++) {
        #pragma unroll
        for (int nt = 0; nt < 8; nt++) {
            const int row = rowBase + wy * 32 + mt * 16 + qrow;
            const int col = colBase + wx * 64 + nt * 8 + qcol;
            const float2 bv = *(const float2*)&bias[col];
            float* o0 = out + (size_t)row * EDIM + col;
            float* o1 = o0 + 8 * EDIM;
            *(float2*)o0 = make_float2(acc[mt][nt][0] + bv.x, acc[mt][nt][1] + bv.y);
            *(float2*)o1 = make_float2(acc[mt][nt][2] + bv.x, acc[mt][nt][3] + bv.y);
        }
    }
}

// ---------------------------------------------------------------------------
extern "C" void kernel_launch(void* const* d_in, const int* in_sizes, int n_in,
                              void* d_out, int out_size) {
    const float* x     = (const float*)d_in[0];
    const float* theta = (const float*)d_in[1];
    const float* W     = (const float*)d_in[2];
    const float* bias  = (const float*)d_in[3];
    float* out = (float*)d_out;

    cudaFuncSetAttribute(out_gemm_mma, cudaFuncAttributeMaxDynamicSharedMemorySize,
                         GSMEM_BYTES);

    qattn_kernel<<<TOKENS / 4, 256>>>(x, theta, W);

    dim3 grid(EDIM / 128, TOKENS / 128);   // (4, 128)
    out_gemm_mma<<<grid, 256, GSMEM_BYTES>>>(bias, out);
}

// round 6
// speedup vs baseline: 8.4885x; 1.0165x over previous
#include <cuda_runtime.h>
#include <cuda_bf16.h>
#include <math_constants.h>

#define TOKENS (8 * 2048)
#define EDIM   512
#define NHEAD  64
#define DK     8

// Split-bf16 operands:  value = hi + lo  (each bf16, stored as ushort)
__device__ unsigned short g_Ah[(size_t)TOKENS * EDIM];
__device__ unsigned short g_Al[(size_t)TOKENS * EDIM];
__device__ unsigned short g_Bh[(size_t)EDIM * EDIM];
__device__ unsigned short g_Bl[(size_t)EDIM * EDIM];

// ---- packed f32x2 helpers (qattn) ----------------------------------------
__device__ __forceinline__ unsigned long long pack2(float lo, float hi) {
    unsigned long long r;
    asm("mov.b64 %0, {%1, %2};" : "=l"(r) : "f"(lo), "f"(hi));
    return r;
}
__device__ __forceinline__ void unpack2(unsigned long long v, float& lo, float& hi) {
    asm("mov.b64 {%0, %1}, %2;" : "=f"(lo), "=f"(hi) : "l"(v));
}
__device__ __forceinline__ unsigned long long fma2(unsigned long long a,
                                                   unsigned long long b,
                                                   unsigned long long c) {
    unsigned long long d;
    asm("fma.rn.f32x2 %0, %1, %2, %3;" : "=l"(d) : "l"(a), "l"(b), "l"(c));
    return d;
}
__device__ __forceinline__ unsigned long long mul2(unsigned long long a,
                                                   unsigned long long b) {
    unsigned long long d;
    asm("mul.rn.f32x2 %0, %1, %2;" : "=l"(d) : "l"(a), "l"(b));
    return d;
}
__device__ __forceinline__ float ex2(float x) {
    float y;
    asm("ex2.approx.f32 %0, %1;" : "=f"(y) : "f"(x));
    return y;
}

// ---- bf16 split helper ----------------------------------------------------
__device__ __forceinline__ void bsplit(float v, unsigned short& h, unsigned short& l) {
    __nv_bfloat16 hb = __float2bfloat16(v);
    h = __bfloat16_as_ushort(hb);
    l = __bfloat16_as_ushort(__float2bfloat16(v - __bfloat162float(hb)));
}

// ---- smem / async / mma helpers ------------------------------------------
__device__ __forceinline__ unsigned smem_u32(const void* p) {
    unsigned a;
    asm("{ .reg .u64 t; cvta.to.shared.u64 t, %1; cvt.u32.u64 %0, t; }" : "=r"(a) : "l"(p));
    return a;
}
__device__ __forceinline__ void cp16(unsigned dst, const void* src) {
    asm volatile("cp.async.cg.shared.global [%0], [%1], 16;" :: "r"(dst), "l"(src));
}
__device__ __forceinline__ void ldsm_x4(unsigned& r0, unsigned& r1, unsigned& r2,
                                        unsigned& r3, unsigned addr) {
    asm volatile("ldmatrix.sync.aligned.m8n8.x4.shared.b16 {%0,%1,%2,%3}, [%4];"
                 : "=r"(r0), "=r"(r1), "=r"(r2), "=r"(r3) : "r"(addr));
}
__device__ __forceinline__ void mma_bf16(float* c, const unsigned* a,
                                         unsigned b0, unsigned b1) {
    asm volatile("mma.sync.aligned.m16n8k16.row.col.f32.bf16.bf16.f32 "
                 "{%0,%1,%2,%3}, {%4,%5,%6,%7}, {%8,%9}, {%0,%1,%2,%3};"
                 : "+f"(c[0]), "+f"(c[1]), "+f"(c[2]), "+f"(c[3])
                 : "r"(a[0]), "r"(a[1]), "r"(a[2]), "r"(a[3]), "r"(b0), "r"(b1));
}

#define SWZ64(o) ((o) ^ (((o) >> 3) & 0x30))

// ---------------------------------------------------------------------------
// Kernel A: quantum attention (single pass) + folded W-split (blocks 0..255).
// ---------------------------------------------------------------------------
__global__ __launch_bounds__(256, 4) void qattn_kernel(const float* __restrict__ x,
                                                       const float* __restrict__ theta,
                                                       const float* __restrict__ W) {
    __shared__ float sproj[4][EDIM];

    // Folded W split: blocks 0..255 each handle 256 float4s (one per thread).
    if (blockIdx.x < 256) {
        const int idx = blockIdx.x * 256 + threadIdx.x;  // 0..65535
        const float4 w = ((const float4*)W)[idx];
        unsigned short h0, h1, h2, h3, l0, l1, l2, l3;
        bsplit(w.x, h0, l0); bsplit(w.y, h1, l1);
        bsplit(w.z, h2, l2); bsplit(w.w, h3, l3);
        uint2 hu, lu;
        hu.x = (unsigned)h0 | ((unsigned)h1 << 16);
        hu.y = (unsigned)h2 | ((unsigned)h3 << 16);
        lu.x = (unsigned)l0 | ((unsigned)l1 << 16);
        lu.y = (unsigned)l2 | ((unsigned)l3 << 16);
        ((uint2*)g_Bh)[idx] = hu;
        ((uint2*)g_Bl)[idx] = lu;
    }

    const int tl = threadIdx.x >> 6;
    const int h  = threadIdx.x & 63;
    const int token = (blockIdx.x << 2) + tl;

    float th[8];
    {
        const float4 t0 = ((const float4*)theta)[0];
        const float4 t1 = ((const float4*)theta)[1];
        th[0] = t0.x; th[1] = t0.y; th[2] = t0.z; th[3] = t0.w;
        th[4] = t1.x; th[5] = t1.y; th[6] = t1.z; th[7] = t1.w;
    }

    // dot-operand copy pre-scaled by (1/sqrt(8)) * log2(e) so the softmax
    // exp becomes a single ex2.approx on the raw horizontal sum.
    const float SL = 0.35355339059327373f * 1.4426950408889634f;
    unsigned long long p2[4];
    {
        const float4* xp = (const float4*)(x + (size_t)token * EDIM + h * DK);
        const float4 a0 = xp[0], a1 = xp[1];
        float p0 = __cosf(a0.x + th[0]), p1 = __cosf(a0.y + th[1]);
        float q0 = __cosf(a0.z + th[2]), q1 = __cosf(a0.w + th[3]);
        float r0 = __cosf(a1.x + th[4]), r1 = __cosf(a1.y + th[5]);
        float s0 = __cosf(a1.z + th[6]), s1 = __cosf(a1.w + th[7]);
        p2[0] = pack2(p0 * SL, p1 * SL); p2[1] = pack2(q0 * SL, q1 * SL);
        p2[2] = pack2(r0 * SL, r1 * SL); p2[3] = pack2(s0 * SL, s1 * SL);
        float4* sp = (float4*)&sproj[tl][h * DK];
        sp[0] = make_float4(p0, p1, q0, q1);
        sp[1] = make_float4(r0, r1, s0, s1);
    }
    __syncthreads();

    unsigned long long acc2[4];
    acc2[0] = acc2[1] = acc2[2] = acc2[3] = pack2(0.f, 0.f);
    float sum = 0.f;

    #pragma unroll 8
    for (int g = 0; g < NHEAD; g++) {
        const ulonglong2* qp = (const ulonglong2*)&sproj[tl][g * DK];
        const ulonglong2 qa = qp[0];
        const ulonglong2 qb = qp[1];

        unsigned long long d2 = mul2(p2[0], qa.x);
        d2 = fma2(p2[1], qa.y, d2);
        d2 = fma2(p2[2], qb.x, d2);
        d2 = fma2(p2[3], qb.y, d2);
        float dlo, dhi;
        unpack2(d2, dlo, dhi);

        const float e = ex2(dlo + dhi);   // = exp(score/sqrt(8))
        sum += e;

        const unsigned long long e2 = pack2(e, e);
        acc2[0] = fma2(e2, qa.x, acc2[0]);
        acc2[1] = fma2(e2, qa.y, acc2[1]);
        acc2[2] = fma2(e2, qb.x, acc2[2]);
        acc2[3] = fma2(e2, qb.y, acc2[3]);
    }

    const float inv = 1.0f / sum;
    float v[8];
    unpack2(acc2[0], v[0], v[1]); unpack2(acc2[1], v[2], v[3]);
    unpack2(acc2[2], v[4], v[5]); unpack2(acc2[3], v[6], v[7]);

    unsigned short hs[8], ls[8];
    #pragma unroll
    for (int i = 0; i < 8; i++) bsplit(v[i] * inv, hs[i], ls[i]);

    // permuted store:  mid[b, h*32 + s/64, (s%64)*8 + d]
    const int b  = token >> 11;
    const int sb = token & 2047;
    const size_t row = (size_t)(b * 2048) + (size_t)(h * 32) + (size_t)(sb >> 6);
    const size_t off = row * EDIM + (size_t)((sb & 63) * DK);

    uint4 hu, lu;
    hu.x = (unsigned)hs[0] | ((unsigned)hs[1] << 16);
    hu.y = (unsigned)hs[2] | ((unsigned)hs[3] << 16);
    hu.z = (unsigned)hs[4] | ((unsigned)hs[5] << 16);
    hu.w = (unsigned)hs[6] | ((unsigned)hs[7] << 16);
    lu.x = (unsigned)ls[0] | ((unsigned)ls[1] << 16);
    lu.y = (unsigned)ls[2] | ((unsigned)ls[3] << 16);
    lu.z = (unsigned)ls[4] | ((unsigned)ls[5] << 16);
    lu.w = (unsigned)ls[6] | ((unsigned)ls[7] << 16);
    *(uint4*)(g_Ah + off) = hu;
    *(uint4*)(g_Al + off) = lu;
}

// ---------------------------------------------------------------------------
// Kernel B: split-bf16 GEMM on mma.sync, 3-stage cp.async pipeline,
// ONE __syncthreads per K-chunk.
// out[16384,512] = (Ah+Al)(Bh+Bl)^T + bias ~= AhBh + AhBl + AlBh
// CTA 128x128, K-chunks of 32 (SW64-swizzled 8KB tiles), 3 stages = 96KB.
// 8 warps in 4(m) x 2(n); warp tile 32x64.
// Stage rotation: compute stage c%3, in-flight load stage (c+1)%3, fill
// stage (c+2)%3 at end of iter c. The fill target's previous readers all
// passed this iteration's top barrier, so no trailing barrier is needed.
// ---------------------------------------------------------------------------
#define TILE_B   8192
#define STAGE_B  32768
#define NSTAGE   3
#define NCHUNK   16
#define GSMEM_BYTES (NSTAGE * STAGE_B)
#define AH_T 0
#define AL_T 1
#define BH_T 2
#define BL_T 3

__device__ __forceinline__ void load_chunk(unsigned sb, int stage, int c,
                                           int rowBase, int colBase, int tid) {
    const unsigned base = sb + stage * STAGE_B;
    #pragma unroll
    for (int i = 0; i < 8; i++) {
        const int v    = i * 256 + tid;   // 0..2047
        const int tile = v >> 9;          // 512 v16 per tile
        const int rem  = v & 511;
        const int r    = rem >> 2;
        const int c16  = rem & 3;
        const unsigned short* src;
        if      (tile == 0) src = g_Ah + (size_t)(rowBase + r) * EDIM;
        else if (tile == 1) src = g_Al + (size_t)(rowBase + r) * EDIM;
        else if (tile == 2) src = g_Bh + (size_t)(colBase + r) * EDIM;
        else                src = g_Bl + (size_t)(colBase + r) * EDIM;
        src += c * 32 + c16 * 8;
        cp16(base + tile * TILE_B + SWZ64(r * 64 + c16 * 16), src);
    }
    asm volatile("cp.async.commit_group;" ::: "memory");
}

__global__ __launch_bounds__(256, 2) void out_gemm_mma(const float* __restrict__ bias,
                                                       float* __restrict__ out) {
    extern __shared__ char smem[];
    const unsigned sb = smem_u32(smem);
    const int tid = threadIdx.x;
    const int wid = tid >> 5;
    const int lid = tid & 31;

    const int rowBase = blockIdx.y * 128;
    const int colBase = blockIdx.x * 128;

    const int wy = wid & 3;    // m: 32 rows each
    const int wx = wid >> 2;   // n: 64 cols each

    const int lr  = lid & 7;
    const int sub = lid >> 3;

    float acc[2][8][4];
    #pragma unroll
    for (int mt = 0; mt < 2; mt++)
        #pragma unroll
        for (int nt = 0; nt < 8; nt++)
            #pragma unroll
            for (int q = 0; q < 4; q++) acc[mt][nt][q] = 0.f;

    // prologue: chunks 0 and 1 into stages 0 and 1
    load_chunk(sb, 0, 0, rowBase, colBase, tid);
    load_chunk(sb, 1, 1, rowBase, colBase, tid);

    int stage = 0;           // = c % 3
    for (int c = 0; c < NCHUNK; c++) {
        if (c < NCHUNK - 1) {
            asm volatile("cp.async.wait_group 1;" ::: "memory");
        } else {
            asm volatile("cp.async.wait_group 0;" ::: "memory");
        }
        __syncthreads();

        const unsigned stg = sb + (unsigned)stage * STAGE_B;

        #pragma unroll
        for (int kk = 0; kk < 2; kk++) {
            const int kb = kk * 32;   // 16 bf16 per k16 step

            unsigned ah[2][4], al[2][4];
            #pragma unroll
            for (int mt = 0; mt < 2; mt++) {
                const int rowA = wy * 32 + mt * 16 + lr + (sub & 1) * 8;
                const int colb = kb + (sub >> 1) * 16;
                const unsigned off = SWZ64(rowA * 64 + colb);
                ldsm_x4(ah[mt][0], ah[mt][1], ah[mt][2], ah[mt][3], stg + AH_T * TILE_B + off);
                ldsm_x4(al[mt][0], al[mt][1], al[mt][2], al[mt][3], stg + AL_T * TILE_B + off);
            }

            #pragma unroll
            for (int nt16 = 0; nt16 < 4; nt16++) {
                const int rowB = wx * 64 + nt16 * 16 + lr + (sub >> 1) * 8;
                const int colb = kb + (sub & 1) * 16;
                const unsigned off = SWZ64(rowB * 64 + colb);
                unsigned bh[4], bl[4];
                ldsm_x4(bh[0], bh[1], bh[2], bh[3], stg + BH_T * TILE_B + off);
                ldsm_x4(bl[0], bl[1], bl[2], bl[3], stg + BL_T * TILE_B + off);

                #pragma unroll
                for (int mt = 0; mt < 2; mt++) {
                    float* c0 = acc[mt][nt16 * 2];
                    float* c1 = acc[mt][nt16 * 2 + 1];
                    mma_bf16(c0, ah[mt], bh[0], bh[1]);
                    mma_bf16(c0, ah[mt], bl[0], bl[1]);
                    mma_bf16(c0, al[mt], bh[0], bh[1]);
                    mma_bf16(c1, ah[mt], bh[2], bh[3]);
                    mma_bf16(c1, ah[mt], bl[2], bl[3]);
                    mma_bf16(c1, al[mt], bh[2], bh[3]);
                }
            }
        }

        // fill chunk c+2 into stage (c+2)%3 — no trailing barrier needed
        if (c + 2 < NCHUNK) {
            int fs = stage + 2;
            if (fs >= NSTAGE) fs -= NSTAGE;
            load_chunk(sb, fs, c + 2, rowBase, colBase, tid);
        }
        if (++stage == NSTAGE) stage = 0;
    }

    // epilogue: bias + store
    const int qrow = lid >> 2;
    const int qcol = (lid & 3) * 2;
    #pragma unroll
    for (int mt = 0; mt < 2; mt++) {
        #pragma unroll
        for (int nt = 0; nt < 8; nt++) {
            const int row = rowBase + wy * 32 + mt * 16 + qrow;
            const int col = colBase + wx * 64 + nt * 8 + qcol;
            const float2 bv = *(const float2*)&bias[col];
            float* o0 = out + (size_t)row * EDIM + col;
            float* o1 = o0 + 8 * EDIM;
            *(float2*)o0 = make_float2(acc[mt][nt][0] + bv.x, acc[mt][nt][1] + bv.y);
            *(float2*)o1 = make_float2(acc[mt][nt][2] + bv.x, acc[mt][nt][3] + bv.y);
        }
    }
}

// ---------------------------------------------------------------------------
extern "C" void kernel_launch(void* const* d_in, const int* in_sizes, int n_in,
                              void* d_out, int out_size) {
    const float* x     = (const float*)d_in[0];
    const float* theta = (const float*)d_in[1];
    const float* W     = (const float*)d_in[2];
    const float* bias  = (const float*)d_in[3];
    float* out = (float*)d_out;

    cudaFuncSetAttribute(out_gemm_mma, cudaFuncAttributeMaxDynamicSharedMemorySize,
                         GSMEM_BYTES);

    qattn_kernel<<<TOKENS / 4, 256>>>(x, theta, W);

    dim3 grid(EDIM / 128, TOKENS / 128);   // (4, 128)
    out_gemm_mma<<<grid, 256, GSMEM_BYTES>>>(bias, out);
}

// round 7
// speedup vs baseline: 8.6532x; 1.0194x over previous
#include <cuda_runtime.h>
#include <cuda_bf16.h>
#include <math_constants.h>

#define TOKENS (8 * 2048)
#define EDIM   512
#define NHEAD  64
#define DK     8

// Split-bf16 operands:  value = hi + lo  (each bf16, stored as ushort)
__device__ unsigned short g_Ah[(size_t)TOKENS * EDIM];
__device__ unsigned short g_Al[(size_t)TOKENS * EDIM];
__device__ unsigned short g_Bh[(size_t)EDIM * EDIM];
__device__ unsigned short g_Bl[(size_t)EDIM * EDIM];

// ---- packed f32x2 helpers -------------------------------------------------
__device__ __forceinline__ unsigned long long pack2(float lo, float hi) {
    unsigned long long r;
    asm("mov.b64 %0, {%1, %2};" : "=l"(r) : "f"(lo), "f"(hi));
    return r;
}
__device__ __forceinline__ void unpack2(unsigned long long v, float& lo, float& hi) {
    asm("mov.b64 {%0, %1}, %2;" : "=f"(lo), "=f"(hi) : "l"(v));
}
__device__ __forceinline__ unsigned long long fma2(unsigned long long a,
                                                   unsigned long long b,
                                                   unsigned long long c) {
    unsigned long long d;
    asm("fma.rn.f32x2 %0, %1, %2, %3;" : "=l"(d) : "l"(a), "l"(b), "l"(c));
    return d;
}
__device__ __forceinline__ unsigned long long mul2(unsigned long long a,
                                                   unsigned long long b) {
    unsigned long long d;
    asm("mul.rn.f32x2 %0, %1, %2;" : "=l"(d) : "l"(a), "l"(b));
    return d;
}
__device__ __forceinline__ float ex2(float x) {
    float y;
    asm("ex2.approx.f32 %0, %1;" : "=f"(y) : "f"(x));
    return y;
}

// ---- bf16 split helper ----------------------------------------------------
__device__ __forceinline__ void bsplit(float v, unsigned short& h, unsigned short& l) {
    __nv_bfloat16 hb = __float2bfloat16(v);
    h = __bfloat16_as_ushort(hb);
    l = __bfloat16_as_ushort(__float2bfloat16(v - __bfloat162float(hb)));
}

// ---- smem / async / mma helpers ------------------------------------------
__device__ __forceinline__ unsigned smem_u32(const void* p) {
    unsigned a;
    asm("{ .reg .u64 t; cvta.to.shared.u64 t, %1; cvt.u32.u64 %0, t; }" : "=r"(a) : "l"(p));
    return a;
}
__device__ __forceinline__ void cp16(unsigned dst, const void* src) {
    asm volatile("cp.async.cg.shared.global [%0], [%1], 16;" :: "r"(dst), "l"(src));
}
__device__ __forceinline__ void ldsm_x4(unsigned& r0, unsigned& r1, unsigned& r2,
                                        unsigned& r3, unsigned addr) {
    asm volatile("ldmatrix.sync.aligned.m8n8.x4.shared.b16 {%0,%1,%2,%3}, [%4];"
                 : "=r"(r0), "=r"(r1), "=r"(r2), "=r"(r3) : "r"(addr));
}
__device__ __forceinline__ void mma_bf16(float* c, const unsigned* a,
                                         unsigned b0, unsigned b1) {
    asm volatile("mma.sync.aligned.m16n8k16.row.col.f32.bf16.bf16.f32 "
                 "{%0,%1,%2,%3}, {%4,%5,%6,%7}, {%8,%9}, {%0,%1,%2,%3};"
                 : "+f"(c[0]), "+f"(c[1]), "+f"(c[2]), "+f"(c[3])
                 : "r"(a[0]), "r"(a[1]), "r"(a[2]), "r"(a[3]), "r"(b0), "r"(b1));
}

#define SWZ64(o) ((o) ^ (((o) >> 3) & 0x30))

// ---------------------------------------------------------------------------
// Kernel A: quantum attention. 256 threads = 16 tokens/CTA; each thread owns
// 4 heads (ht, ht+16, ht+32, ht+48) of one token. Per g, ONE LDS.128 pair per
// warp serves 2 tokens x 4 heads -> smem crossbar load cut 4x vs 1-head/thread.
// Single pass softmax (scores bounded, no max needed). Blocks 0..255 also
// split W into hi/lo bf16.
// ---------------------------------------------------------------------------
__global__ __launch_bounds__(256, 2) void qattn_kernel(const float* __restrict__ x,
                                                       const float* __restrict__ theta,
                                                       const float* __restrict__ W) {
    __shared__ float sproj[16][EDIM];   // 32 KB

    // Folded W split: blocks 0..255 each handle 256 float4s (one per thread).
    if (blockIdx.x < 256) {
        const int idx = blockIdx.x * 256 + threadIdx.x;  // 0..65535
        const float4 w = ((const float4*)W)[idx];
        unsigned short h0, h1, h2, h3, l0, l1, l2, l3;
        bsplit(w.x, h0, l0); bsplit(w.y, h1, l1);
        bsplit(w.z, h2, l2); bsplit(w.w, h3, l3);
        uint2 hu, lu;
        hu.x = (unsigned)h0 | ((unsigned)h1 << 16);
        hu.y = (unsigned)h2 | ((unsigned)h3 << 16);
        lu.x = (unsigned)l0 | ((unsigned)l1 << 16);
        lu.y = (unsigned)l2 | ((unsigned)l3 << 16);
        ((uint2*)g_Bh)[idx] = hu;
        ((uint2*)g_Bl)[idx] = lu;
    }

    const int tl = threadIdx.x >> 4;    // token slot 0..15
    const int ht = threadIdx.x & 15;    // head group: heads ht + 16*j
    const int token = (blockIdx.x << 4) + tl;

    float th[8];
    {
        const float4 t0 = ((const float4*)theta)[0];
        const float4 t1 = ((const float4*)theta)[1];
        th[0] = t0.x; th[1] = t0.y; th[2] = t0.z; th[3] = t0.w;
        th[4] = t1.x; th[5] = t1.y; th[6] = t1.z; th[7] = t1.w;
    }

    // scaled by (1/sqrt(8)) * log2(e): softmax exp -> one ex2 on the raw sum
    const float SL = 0.35355339059327373f * 1.4426950408889634f;

    // proj rows for this thread's 4 heads: scaled copy in regs, raw in smem.
    unsigned long long p2s[4][4];
    {
        const float* xb = x + (size_t)token * EDIM;
        #pragma unroll
        for (int j = 0; j < 4; j++) {
            const int h = ht + 16 * j;
            const float4* xp = (const float4*)(xb + h * DK);
            const float4 a0 = xp[0], a1 = xp[1];
            float c0 = __cosf(a0.x + th[0]), c1 = __cosf(a0.y + th[1]);
            float c2 = __cosf(a0.z + th[2]), c3 = __cosf(a0.w + th[3]);
            float c4 = __cosf(a1.x + th[4]), c5 = __cosf(a1.y + th[5]);
            float c6 = __cosf(a1.z + th[6]), c7 = __cosf(a1.w + th[7]);
            p2s[j][0] = pack2(c0 * SL, c1 * SL);
            p2s[j][1] = pack2(c2 * SL, c3 * SL);
            p2s[j][2] = pack2(c4 * SL, c5 * SL);
            p2s[j][3] = pack2(c6 * SL, c7 * SL);
            float4* sp = (float4*)&sproj[tl][h * DK];
            sp[0] = make_float4(c0, c1, c2, c3);
            sp[1] = make_float4(c4, c5, c6, c7);
        }
    }
    __syncthreads();

    unsigned long long acc2[4][4];
    float sum[4];
    #pragma unroll
    for (int j = 0; j < 4; j++) {
        acc2[j][0] = acc2[j][1] = acc2[j][2] = acc2[j][3] = pack2(0.f, 0.f);
        sum[j] = 0.f;
    }

    #pragma unroll 4
    for (int g = 0; g < NHEAD; g++) {
        const ulonglong2* qp = (const ulonglong2*)&sproj[tl][g * DK];
        const ulonglong2 qa = qp[0];   // floats 0..3
        const ulonglong2 qb = qp[1];   // floats 4..7

        #pragma unroll
        for (int j = 0; j < 4; j++) {
            unsigned long long d2 = mul2(p2s[j][0], qa.x);
            d2 = fma2(p2s[j][1], qa.y, d2);
            d2 = fma2(p2s[j][2], qb.x, d2);
            d2 = fma2(p2s[j][3], qb.y, d2);
            float dlo, dhi;
            unpack2(d2, dlo, dhi);

            const float e = ex2(dlo + dhi);   // exp(score/sqrt(8))
            sum[j] += e;

            const unsigned long long e2 = pack2(e, e);
            acc2[j][0] = fma2(e2, qa.x, acc2[j][0]);
            acc2[j][1] = fma2(e2, qa.y, acc2[j][1]);
            acc2[j][2] = fma2(e2, qb.x, acc2[j][2]);
            acc2[j][3] = fma2(e2, qb.y, acc2[j][3]);
        }
    }

    // epilogue: normalize, split to bf16 hi/lo, permuted store
    const int b  = token >> 11;
    const int sb = token & 2047;
    const size_t rowTail = (size_t)(b * 2048) + (size_t)(sb >> 6);
    const size_t colOff  = (size_t)((sb & 63) * DK);

    #pragma unroll
    for (int j = 0; j < 4; j++) {
        const float inv = 1.0f / sum[j];
        float v[8];
        unpack2(acc2[j][0], v[0], v[1]); unpack2(acc2[j][1], v[2], v[3]);
        unpack2(acc2[j][2], v[4], v[5]); unpack2(acc2[j][3], v[6], v[7]);

        unsigned short hs[8], ls[8];
        #pragma unroll
        for (int i = 0; i < 8; i++) bsplit(v[i] * inv, hs[i], ls[i]);

        const int h = ht + 16 * j;
        const size_t off = (rowTail + (size_t)(h * 32)) * EDIM + colOff;

        uint4 hu, lu;
        hu.x = (unsigned)hs[0] | ((unsigned)hs[1] << 16);
        hu.y = (unsigned)hs[2] | ((unsigned)hs[3] << 16);
        hu.z = (unsigned)hs[4] | ((unsigned)hs[5] << 16);
        hu.w = (unsigned)hs[6] | ((unsigned)hs[7] << 16);
        lu.x = (unsigned)ls[0] | ((unsigned)ls[1] << 16);
        lu.y = (unsigned)ls[2] | ((unsigned)ls[3] << 16);
        lu.z = (unsigned)ls[4] | ((unsigned)ls[5] << 16);
        lu.w = (unsigned)ls[6] | ((unsigned)ls[7] << 16);
        *(uint4*)(g_Ah + off) = hu;
        *(uint4*)(g_Al + off) = lu;
    }
}

// ---------------------------------------------------------------------------
// Kernel B: split-bf16 GEMM on mma.sync, 3-stage cp.async pipeline,
// one __syncthreads per K-chunk.  (unchanged from R6 — near HMMA floor)
// ---------------------------------------------------------------------------
#define TILE_B   8192
#define STAGE_B  32768
#define NSTAGE   3
#define NCHUNK   16
#define GSMEM_BYTES (NSTAGE * STAGE_B)
#define AH_T 0
#define AL_T 1
#define BH_T 2
#define BL_T 3

__device__ __forceinline__ void load_chunk(unsigned sb, int stage, int c,
                                           int rowBase, int colBase, int tid) {
    const unsigned base = sb + stage * STAGE_B;
    #pragma unroll
    for (int i = 0; i < 8; i++) {
        const int v    = i * 256 + tid;   // 0..2047
        const int tile = v >> 9;          // 512 v16 per tile
        const int rem  = v & 511;
        const int r    = rem >> 2;
        const int c16  = rem & 3;
        const unsigned short* src;
        if      (tile == 0) src = g_Ah + (size_t)(rowBase + r) * EDIM;
        else if (tile == 1) src = g_Al + (size_t)(rowBase + r) * EDIM;
        else if (tile == 2) src = g_Bh + (size_t)(colBase + r) * EDIM;
        else                src = g_Bl + (size_t)(colBase + r) * EDIM;
        src += c * 32 + c16 * 8;
        cp16(base + tile * TILE_B + SWZ64(r * 64 + c16 * 16), src);
    }
    asm volatile("cp.async.commit_group;" ::: "memory");
}

__global__ __launch_bounds__(256, 2) void out_gemm_mma(const float* __restrict__ bias,
                                                       float* __restrict__ out) {
    extern __shared__ char smem[];
    const unsigned sb = smem_u32(smem);
    const int tid = threadIdx.x;
    const int wid = tid >> 5;
    const int lid = tid & 31;

    const int rowBase = blockIdx.y * 128;
    const int colBase = blockIdx.x * 128;

    const int wy = wid & 3;    // m: 32 rows each
    const int wx = wid >> 2;   // n: 64 cols each

    const int lr  = lid & 7;
    const int sub = lid >> 3;

    float acc[2][8][4];
    #pragma unroll
    for (int mt = 0; mt < 2; mt++)
        #pragma unroll
        for (int nt = 0; nt < 8; nt++)
            #pragma unroll
            for (int q = 0; q < 4; q++) acc[mt][nt][q] = 0.f;

    load_chunk(sb, 0, 0, rowBase, colBase, tid);
    load_chunk(sb, 1, 1, rowBase, colBase, tid);

    int stage = 0;           // = c % 3
    for (int c = 0; c < NCHUNK; c++) {
        if (c < NCHUNK - 1) {
            asm volatile("cp.async.wait_group 1;" ::: "memory");
        } else {
            asm volatile("cp.async.wait_group 0;" ::: "memory");
        }
        __syncthreads();

        const unsigned stg = sb + (unsigned)stage * STAGE_B;

        #pragma unroll
        for (int kk = 0; kk < 2; kk++) {
            const int kb = kk * 32;

            unsigned ah[2][4], al[2][4];
            #pragma unroll
            for (int mt = 0; mt < 2; mt++) {
                const int rowA = wy * 32 + mt * 16 + lr + (sub & 1) * 8;
                const int colb = kb + (sub >> 1) * 16;
                const unsigned off = SWZ64(rowA * 64 + colb);
                ldsm_x4(ah[mt][0], ah[mt][1], ah[mt][2], ah[mt][3], stg + AH_T * TILE_B + off);
                ldsm_x4(al[mt][0], al[mt][1], al[mt][2], al[mt][3], stg + AL_T * TILE_B + off);
            }

            #pragma unroll
            for (int nt16 = 0; nt16 < 4; nt16++) {
                const int rowB = wx * 64 + nt16 * 16 + lr + (sub >> 1) * 8;
                const int colb = kb + (sub & 1) * 16;
                const unsigned off = SWZ64(rowB * 64 + colb);
                unsigned bh[4], bl[4];
                ldsm_x4(bh[0], bh[1], bh[2], bh[3], stg + BH_T * TILE_B + off);
                ldsm_x4(bl[0], bl[1], bl[2], bl[3], stg + BL_T * TILE_B + off);

                #pragma unroll
                for (int mt = 0; mt < 2; mt++) {
                    float* c0 = acc[mt][nt16 * 2];
                    float* c1 = acc[mt][nt16 * 2 + 1];
                    mma_bf16(c0, ah[mt], bh[0], bh[1]);
                    mma_bf16(c0, ah[mt], bl[0], bl[1]);
                    mma_bf16(c0, al[mt], bh[0], bh[1]);
                    mma_bf16(c1, ah[mt], bh[2], bh[3]);
                    mma_bf16(c1, ah[mt], bl[2], bl[3]);
                    mma_bf16(c1, al[mt], bh[2], bh[3]);
                }
            }
        }

        if (c + 2 < NCHUNK) {
            int fs = stage + 2;
            if (fs >= NSTAGE) fs -= NSTAGE;
            load_chunk(sb, fs, c + 2, rowBase, colBase, tid);
        }
        if (++stage == NSTAGE) stage = 0;
    }

    // epilogue: bias + store
    const int qrow = lid >> 2;
    const int qcol = (lid & 3) * 2;
    #pragma unroll
    for (int mt = 0; mt < 2; mt++) {
        #pragma unroll
        for (int nt = 0; nt < 8; nt++) {
            const int row = rowBase + wy * 32 + mt * 16 + qrow;
            const int col = colBase + wx * 64 + nt * 8 + qcol;
            const float2 bv = *(const float2*)&bias[col];
            float* o0 = out + (size_t)row * EDIM + col;
            float* o1 = o0 + 8 * EDIM;
            *(float2*)o0 = make_float2(acc[mt][nt][0] + bv.x, acc[mt][nt][1] + bv.y);
            *(float2*)o1 = make_float2(acc[mt][nt][2] + bv.x, acc[mt][nt][3] + bv.y);
        }
    }
}

// ---------------------------------------------------------------------------
extern "C" void kernel_launch(void* const* d_in, const int* in_sizes, int n_in,
                              void* d_out, int out_size) {
    const float* x     = (const float*)d_in[0];
    const float* theta = (const float*)d_in[1];
    const float* W     = (const float*)d_in[2];
    const float* bias  = (const float*)d_in[3];
    float* out = (float*)d_out;

    cudaFuncSetAttribute(out_gemm_mma, cudaFuncAttributeMaxDynamicSharedMemorySize,
                         GSMEM_BYTES);

    qattn_kernel<<<TOKENS / 16, 256>>>(x, theta, W);

    dim3 grid(EDIM / 128, TOKENS / 128);   // (4, 128)
    out_gemm_mma<<<grid, 256, GSMEM_BYTES>>>(bias, out);
}

// round 8
// speedup vs baseline: 9.5831x; 1.1075x over previous
#include <cuda_runtime.h>
#include <cuda_bf16.h>
#include <math_constants.h>

#define TOKENS (8 * 2048)
#define EDIM   512
#define NHEAD  64
#define DK     8

// Split-bf16 operands:  value = hi + lo  (each bf16, stored as ushort)
__device__ unsigned short g_Ah[(size_t)TOKENS * EDIM];
__device__ unsigned short g_Al[(size_t)TOKENS * EDIM];
__device__ unsigned short g_Bh[(size_t)EDIM * EDIM];
__device__ unsigned short g_Bl[(size_t)EDIM * EDIM];

// ---- helpers --------------------------------------------------------------
__device__ __forceinline__ float ex2(float x) {
    float y; asm("ex2.approx.f32 %0, %1;" : "=f"(y) : "f"(x)); return y;
}
__device__ __forceinline__ float rcpa(float x) {
    float y; asm("rcp.approx.f32 %0, %1;" : "=f"(y) : "f"(x)); return y;
}
// pack {lo16=a.hi16, hi16=b.hi16}: truncated-bf16 pair (a -> low half)
__device__ __forceinline__ unsigned prmt_hi(float a, float b) {
    unsigned d;
    asm("prmt.b32 %0, %1, %2, 0x7632;" : "=r"(d) : "r"(__float_as_uint(a)), "r"(__float_as_uint(b)));
    return d;
}
// rounded bf16x2: low half = cvt(lo_), high half = cvt(hi_)
__device__ __forceinline__ unsigned cvtbf2(float hi_, float lo_) {
    unsigned d;
    asm("cvt.rn.bf16x2.f32 %0, %1, %2;" : "=r"(d) : "f"(hi_), "f"(lo_));
    return d;
}
__device__ __forceinline__ float btrunc(float v) {   // exact bf16-truncation
    return __uint_as_float(__float_as_uint(v) & 0xFFFF0000u);
}
__device__ __forceinline__ void bsplit(float v, unsigned short& h, unsigned short& l) {
    __nv_bfloat16 hb = __float2bfloat16(v);
    h = __bfloat16_as_ushort(hb);
    l = __bfloat16_as_ushort(__float2bfloat16(v - __bfloat162float(hb)));
}
__device__ __forceinline__ unsigned smem_u32(const void* p) {
    unsigned a;
    asm("{ .reg .u64 t; cvta.to.shared.u64 t, %1; cvt.u32.u64 %0, t; }" : "=r"(a) : "l"(p));
    return a;
}
__device__ __forceinline__ void cp16(unsigned dst, const void* src) {
    asm volatile("cp.async.cg.shared.global [%0], [%1], 16;" :: "r"(dst), "l"(src));
}
__device__ __forceinline__ void ldsm_x4(unsigned& r0, unsigned& r1, unsigned& r2,
                                        unsigned& r3, unsigned addr) {
    asm volatile("ldmatrix.sync.aligned.m8n8.x4.shared.b16 {%0,%1,%2,%3}, [%4];"
                 : "=r"(r0), "=r"(r1), "=r"(r2), "=r"(r3) : "r"(addr));
}
__device__ __forceinline__ void ldsm_x2(unsigned& r0, unsigned& r1, unsigned addr) {
    asm volatile("ldmatrix.sync.aligned.m8n8.x2.shared.b16 {%0,%1}, [%2];"
                 : "=r"(r0), "=r"(r1) : "r"(addr));
}
__device__ __forceinline__ void mma_bf16(float* c, const unsigned* a,
                                         unsigned b0, unsigned b1) {
    asm volatile("mma.sync.aligned.m16n8k16.row.col.f32.bf16.bf16.f32 "
                 "{%0,%1,%2,%3}, {%4,%5,%6,%7}, {%8,%9}, {%0,%1,%2,%3};"
                 : "+f"(c[0]), "+f"(c[1]), "+f"(c[2]), "+f"(c[3])
                 : "r"(a[0]), "r"(a[1]), "r"(a[2]), "r"(a[3]), "r"(b0), "r"(b1));
}

#define SWZ64(o) ((o) ^ (((o) >> 3) & 0x30))

// ---------------------------------------------------------------------------
// Kernel A: tensor-core quantum attention, 1 warp per token (8 tokens/CTA).
// Per-token smem (warp-private):
//   PH/PL: P scaled by s=sqrt(SL), g-major: 64 rows x 8 bf16 (16B rows)
//   TH/TL: P raw, d-major: 8 rows x 64 bf16 (144B padded rows, conflict-free)
// S = (sP)(sP)^T = SL * P P^T  -> ex2 = exp(score/sqrt(8)).
// attn-slice = E (16x64) @ T (64x8), E frags packed straight from S c-frags.
// Split-bf16 3-term products in both stages. Blocks 0..255 also split W.
// ---------------------------------------------------------------------------
#define TOK_SZ 4352
#define PH_OFF 0
#define PL_OFF 1024
#define TH_OFF 2048
#define TL_OFF 3200

__global__ __launch_bounds__(256, 2) void qattn_tc(const float* __restrict__ x,
                                                   const float* __restrict__ theta,
                                                   const float* __restrict__ W) {
    __shared__ char sm[8 * TOK_SZ];

    const int tid = threadIdx.x;
    const int wid = tid >> 5;
    const int lid = tid & 31;

    // Folded W split
    if (blockIdx.x < 256) {
        const int idx = blockIdx.x * 256 + tid;
        const float4 w = ((const float4*)W)[idx];
        unsigned short h0, h1, h2, h3, l0, l1, l2, l3;
        bsplit(w.x, h0, l0); bsplit(w.y, h1, l1);
        bsplit(w.z, h2, l2); bsplit(w.w, h3, l3);
        uint2 hu, lu;
        hu.x = (unsigned)h0 | ((unsigned)h1 << 16);
        hu.y = (unsigned)h2 | ((unsigned)h3 << 16);
        lu.x = (unsigned)l0 | ((unsigned)l1 << 16);
        lu.y = (unsigned)l2 | ((unsigned)l3 << 16);
        ((uint2*)g_Bh)[idx] = hu;
        ((uint2*)g_Bl)[idx] = lu;
    }

    const int token = blockIdx.x * 8 + wid;
    const unsigned base = smem_u32(sm) + wid * TOK_SZ;

    float th[8];
    {
        const float4 t0 = ((const float4*)theta)[0];
        const float4 t1 = ((const float4*)theta)[1];
        th[0] = t0.x; th[1] = t0.y; th[2] = t0.z; th[3] = t0.w;
        th[4] = t1.x; th[5] = t1.y; th[6] = t1.z; th[7] = t1.w;
    }

    const float SL = 0.35355339059327373f * 1.4426950408889634f;  // (1/sqrt8)*log2e
    const float s  = 0.7142224053f;                               // sqrt(SL)

    // ---- P generation: lane handles rows g=2*lid and 2*lid+1 --------------
    {
        const float* xb = x + (size_t)token * EDIM + lid * 16;
        const float4 v0 = ((const float4*)xb)[0];
        const float4 v1 = ((const float4*)xb)[1];
        const float4 v2 = ((const float4*)xb)[2];
        const float4 v3 = ((const float4*)xb)[3];
        float pa[8], pb[8];
        pa[0] = __cosf(v0.x + th[0]); pa[1] = __cosf(v0.y + th[1]);
        pa[2] = __cosf(v0.z + th[2]); pa[3] = __cosf(v0.w + th[3]);
        pa[4] = __cosf(v1.x + th[4]); pa[5] = __cosf(v1.y + th[5]);
        pa[6] = __cosf(v1.z + th[6]); pa[7] = __cosf(v1.w + th[7]);
        pb[0] = __cosf(v2.x + th[0]); pb[1] = __cosf(v2.y + th[1]);
        pb[2] = __cosf(v2.z + th[2]); pb[3] = __cosf(v2.w + th[3]);
        pb[4] = __cosf(v3.x + th[4]); pb[5] = __cosf(v3.y + th[5]);
        pb[6] = __cosf(v3.z + th[6]); pb[7] = __cosf(v3.w + th[7]);

        // T (raw, d-major): row d, col pair (2*lid, 2*lid+1)
        #pragma unroll
        for (int d = 0; d < 8; d++) {
            const unsigned hp = prmt_hi(pa[d], pb[d]);
            *(unsigned*)(sm + (base - smem_u32(sm)) + TH_OFF + d * 144 + lid * 4) = hp;
            const float la = pa[d] - btrunc(pa[d]);
            const float lb = pb[d] - btrunc(pb[d]);
            *(unsigned*)(sm + (base - smem_u32(sm)) + TL_OFF + d * 144 + lid * 4) = cvtbf2(lb, la);
        }

        // P-major (scaled): rows 2*lid, 2*lid+1, 8 bf16 each
        float sa[8], sb2[8];
        #pragma unroll
        for (int i = 0; i < 8; i++) { sa[i] = pa[i] * s; sb2[i] = pb[i] * s; }

        char* smp = sm + (base - smem_u32(sm));
        uint4 hrow, lrow;
        hrow.x = prmt_hi(sa[0], sa[1]); hrow.y = prmt_hi(sa[2], sa[3]);
        hrow.z = prmt_hi(sa[4], sa[5]); hrow.w = prmt_hi(sa[6], sa[7]);
        lrow.x = cvtbf2(sa[1] - btrunc(sa[1]), sa[0] - btrunc(sa[0]));
        lrow.y = cvtbf2(sa[3] - btrunc(sa[3]), sa[2] - btrunc(sa[2]));
        lrow.z = cvtbf2(sa[5] - btrunc(sa[5]), sa[4] - btrunc(sa[4]));
        lrow.w = cvtbf2(sa[7] - btrunc(sa[7]), sa[6] - btrunc(sa[6]));
        *(uint4*)(smp + PH_OFF + (2 * lid) * 16) = hrow;
        *(uint4*)(smp + PL_OFF + (2 * lid) * 16) = lrow;
        hrow.x = prmt_hi(sb2[0], sb2[1]); hrow.y = prmt_hi(sb2[2], sb2[3]);
        hrow.z = prmt_hi(sb2[4], sb2[5]); hrow.w = prmt_hi(sb2[6], sb2[7]);
        lrow.x = cvtbf2(sb2[1] - btrunc(sb2[1]), sb2[0] - btrunc(sb2[0]));
        lrow.y = cvtbf2(sb2[3] - btrunc(sb2[3]), sb2[2] - btrunc(sb2[2]));
        lrow.z = cvtbf2(sb2[5] - btrunc(sb2[5]), sb2[4] - btrunc(sb2[4]));
        lrow.w = cvtbf2(sb2[7] - btrunc(sb2[7]), sb2[6] - btrunc(sb2[6]));
        *(uint4*)(smp + PH_OFF + (2 * lid + 1) * 16) = hrow;
        *(uint4*)(smp + PL_OFF + (2 * lid + 1) * 16) = lrow;
    }
    __syncwarp();

    // ---- hoisted A-stage B-frags from T (invariant across slices) ---------
    unsigned bTh[4][2], bTl[4][2];
    #pragma unroll
    for (int t = 0; t < 2; t++) {
        const unsigned addrh = base + TH_OFF + (lid & 7) * 144 + t * 64 + (lid >> 3) * 16;
        const unsigned addrl = base + TL_OFF + (lid & 7) * 144 + t * 64 + (lid >> 3) * 16;
        ldsm_x4(bTh[2 * t][0], bTh[2 * t][1], bTh[2 * t + 1][0], bTh[2 * t + 1][1], addrh);
        ldsm_x4(bTl[2 * t][0], bTl[2 * t][1], bTl[2 * t + 1][0], bTl[2 * t + 1][1], addrl);
    }

    // permuted-store constants
    const int bI  = token >> 11;
    const int sbI = token & 2047;
    const size_t rowTail = (size_t)(bI * 2048) + (size_t)(sbI >> 6);
    const int colOff = (sbI & 63) * DK + 2 * (lid & 3);

    // ---- slice loop: 4 x (16 rows of S + softmax + attn) ------------------
    #pragma unroll 1
    for (int ms = 0; ms < 4; ms++) {
        // A-frags of scaled P (k16, upper k zero)
        unsigned ah4[4] = {0u, 0u, 0u, 0u}, al4[4] = {0u, 0u, 0u, 0u};
        ldsm_x2(ah4[0], ah4[1], base + PH_OFF + (16 * ms + (lid & 15)) * 16);
        ldsm_x2(al4[0], al4[1], base + PL_OFF + (16 * ms + (lid & 15)) * 16);

        // B-frags: all 64 g-rows of scaled P (8 n8-tiles per component)
        unsigned bh[8], bl[8];
        ldsm_x4(bh[0], bh[1], bh[2], bh[3], base + PH_OFF + lid * 16);
        ldsm_x4(bh[4], bh[5], bh[6], bh[7], base + PH_OFF + (lid + 32) * 16);
        ldsm_x4(bl[0], bl[1], bl[2], bl[3], base + PL_OFF + lid * 16);
        ldsm_x4(bl[4], bl[5], bl[6], bl[7], base + PL_OFF + (lid + 32) * 16);

        float c[8][4];
        #pragma unroll
        for (int nt = 0; nt < 8; nt++) {
            c[nt][0] = c[nt][1] = c[nt][2] = c[nt][3] = 0.f;
            mma_bf16(c[nt], ah4, bh[nt], 0u);
            mma_bf16(c[nt], ah4, bl[nt], 0u);
            mma_bf16(c[nt], al4, bh[nt], 0u);
        }

        // softmax numerators + row sums (fp32, exact)
        float sum0 = 0.f, sum1 = 0.f;
        #pragma unroll
        for (int nt = 0; nt < 8; nt++) {
            c[nt][0] = ex2(c[nt][0]); c[nt][1] = ex2(c[nt][1]);
            c[nt][2] = ex2(c[nt][2]); c[nt][3] = ex2(c[nt][3]);
            sum0 += c[nt][0] + c[nt][1];
            sum1 += c[nt][2] + c[nt][3];
        }
        sum0 += __shfl_xor_sync(0xffffffffu, sum0, 1);
        sum0 += __shfl_xor_sync(0xffffffffu, sum0, 2);
        sum1 += __shfl_xor_sync(0xffffffffu, sum1, 1);
        sum1 += __shfl_xor_sync(0xffffffffu, sum1, 2);
        const float inv0 = rcpa(sum0);
        const float inv1 = rcpa(sum1);

        // pack E into A-frags (hi via trunc-prmt, lo via cvt)
        unsigned Eh[4][4], El[4][4];
        #pragma unroll
        for (int kt = 0; kt < 4; kt++) {
            const int n0 = 2 * kt, n1 = 2 * kt + 1;
            Eh[kt][0] = prmt_hi(c[n0][0], c[n0][1]);
            Eh[kt][1] = prmt_hi(c[n0][2], c[n0][3]);
            Eh[kt][2] = prmt_hi(c[n1][0], c[n1][1]);
            Eh[kt][3] = prmt_hi(c[n1][2], c[n1][3]);
            El[kt][0] = cvtbf2(c[n0][1] - btrunc(c[n0][1]), c[n0][0] - btrunc(c[n0][0]));
            El[kt][1] = cvtbf2(c[n0][3] - btrunc(c[n0][3]), c[n0][2] - btrunc(c[n0][2]));
            El[kt][2] = cvtbf2(c[n1][1] - btrunc(c[n1][1]), c[n1][0] - btrunc(c[n1][0]));
            El[kt][3] = cvtbf2(c[n1][3] - btrunc(c[n1][3]), c[n1][2] - btrunc(c[n1][2]));
        }

        // attn slice = E @ T   (16 x 8)
        float o[4] = {0.f, 0.f, 0.f, 0.f};
        #pragma unroll
        for (int kt = 0; kt < 4; kt++) {
            mma_bf16(o, Eh[kt], bTh[kt][0], bTh[kt][1]);
            mma_bf16(o, Eh[kt], bTl[kt][0], bTl[kt][1]);
            mma_bf16(o, El[kt], bTh[kt][0], bTh[kt][1]);
        }
        o[0] *= inv0; o[1] *= inv0; o[2] *= inv1; o[3] *= inv1;

        // split + permuted store: row h = 16*ms + lid/4 (+8), col pair colOff
        const int h0 = 16 * ms + (lid >> 2);
        const size_t off0 = (rowTail + (size_t)(h0 * 32)) * EDIM + colOff;
        const size_t off1 = (rowTail + (size_t)((h0 + 8) * 32)) * EDIM + colOff;
        *(unsigned*)(g_Ah + off0) = prmt_hi(o[0], o[1]);
        *(unsigned*)(g_Al + off0) = cvtbf2(o[1] - btrunc(o[1]), o[0] - btrunc(o[0]));
        *(unsigned*)(g_Ah + off1) = prmt_hi(o[2], o[3]);
        *(unsigned*)(g_Al + off1) = cvtbf2(o[3] - btrunc(o[3]), o[2] - btrunc(o[2]));
    }
}

// ---------------------------------------------------------------------------
// Kernel B: split-bf16 GEMM on mma.sync, 3-stage cp.async pipeline (R6).
// ---------------------------------------------------------------------------
#define TILE_B   8192
#define STAGE_B  32768
#define NSTAGE   3
#define NCHUNK   16
#define GSMEM_BYTES (NSTAGE * STAGE_B)
#define AH_T 0
#define AL_T 1
#define BH_T 2
#define BL_T 3

__device__ __forceinline__ void load_chunk(unsigned sb, int stage, int c,
                                           int rowBase, int colBase, int tid) {
    const unsigned base = sb + stage * STAGE_B;
    #pragma unroll
    for (int i = 0; i < 8; i++) {
        const int v    = i * 256 + tid;
        const int tile = v >> 9;
        const int rem  = v & 511;
        const int r    = rem >> 2;
        const int c16  = rem & 3;
        const unsigned short* src;
        if      (tile == 0) src = g_Ah + (size_t)(rowBase + r) * EDIM;
        else if (tile == 1) src = g_Al + (size_t)(rowBase + r) * EDIM;
        else if (tile == 2) src = g_Bh + (size_t)(colBase + r) * EDIM;
        else                src = g_Bl + (size_t)(colBase + r) * EDIM;
        src += c * 32 + c16 * 8;
        cp16(base + tile * TILE_B + SWZ64(r * 64 + c16 * 16), src);
    }
    asm volatile("cp.async.commit_group;" ::: "memory");
}

__global__ __launch_bounds__(256, 2) void out_gemm_mma(const float* __restrict__ bias,
                                                       float* __restrict__ out) {
    extern __shared__ char smem[];
    const unsigned sb = smem_u32(smem);
    const int tid = threadIdx.x;
    const int wid = tid >> 5;
    const int lid = tid & 31;

    const int rowBase = blockIdx.y * 128;
    const int colBase = blockIdx.x * 128;

    const int wy = wid & 3;
    const int wx = wid >> 2;
    const int lr  = lid & 7;
    const int sub = lid >> 3;

    float acc[2][8][4];
    #pragma unroll
    for (int mt = 0; mt < 2; mt++)
        #pragma unroll
        for (int nt = 0; nt < 8; nt++)
            #pragma unroll
            for (int q = 0; q < 4; q++) acc[mt][nt][q] = 0.f;

    load_chunk(sb, 0, 0, rowBase, colBase, tid);
    load_chunk(sb, 1, 1, rowBase, colBase, tid);

    int stage = 0;
    for (int c = 0; c < NCHUNK; c++) {
        if (c < NCHUNK - 1) {
            asm volatile("cp.async.wait_group 1;" ::: "memory");
        } else {
            asm volatile("cp.async.wait_group 0;" ::: "memory");
        }
        __syncthreads();

        const unsigned stg = sb + (unsigned)stage * STAGE_B;

        #pragma unroll
        for (int kk = 0; kk < 2; kk++) {
            const int kb = kk * 32;

            unsigned ah[2][4], al[2][4];
            #pragma unroll
            for (int mt = 0; mt < 2; mt++) {
                const int rowA = wy * 32 + mt * 16 + lr + (sub & 1) * 8;
                const int colb = kb + (sub >> 1) * 16;
                const unsigned off = SWZ64(rowA * 64 + colb);
                ldsm_x4(ah[mt][0], ah[mt][1], ah[mt][2], ah[mt][3], stg + AH_T * TILE_B + off);
                ldsm_x4(al[mt][0], al[mt][1], al[mt][2], al[mt][3], stg + AL_T * TILE_B + off);
            }

            #pragma unroll
            for (int nt16 = 0; nt16 < 4; nt16++) {
                const int rowB = wx * 64 + nt16 * 16 + lr + (sub >> 1) * 8;
                const int colb = kb + (sub & 1) * 16;
                const unsigned off = SWZ64(rowB * 64 + colb);
                unsigned bh[4], bl[4];
                ldsm_x4(bh[0], bh[1], bh[2], bh[3], stg + BH_T * TILE_B + off);
                ldsm_x4(bl[0], bl[1], bl[2], bl[3], stg + BL_T * TILE_B + off);

                #pragma unroll
                for (int mt = 0; mt < 2; mt++) {
                    float* c0 = acc[mt][nt16 * 2];
                    float* c1 = acc[mt][nt16 * 2 + 1];
                    mma_bf16(c0, ah[mt], bh[0], bh[1]);
                    mma_bf16(c0, ah[mt], bl[0], bl[1]);
                    mma_bf16(c0, al[mt], bh[0], bh[1]);
                    mma_bf16(c1, ah[mt], bh[2], bh[3]);
                    mma_bf16(c1, ah[mt], bl[2], bl[3]);
                    mma_bf16(c1, al[mt], bh[2], bh[3]);
                }
            }
        }

        if (c + 2 < NCHUNK) {
            int fs = stage + 2;
            if (fs >= NSTAGE) fs -= NSTAGE;
            load_chunk(sb, fs, c + 2, rowBase, colBase, tid);
        }
        if (++stage == NSTAGE) stage = 0;
    }

    const int qrow = lid >> 2;
    const int qcol = (lid & 3) * 2;
    #pragma unroll
    for (int mt = 0; mt < 2; mt++) {
        #pragma unroll
        for (int nt = 0; nt < 8; nt++) {
            const int row = rowBase + wy * 32 + mt * 16 + qrow;
            const int col = colBase + wx * 64 + nt * 8 + qcol;
            const float2 bv = *(const float2*)&bias[col];
            float* o0 = out + (size_t)row * EDIM + col;
            float* o1 = o0 + 8 * EDIM;
            *(float2*)o0 = make_float2(acc[mt][nt][0] + bv.x, acc[mt][nt][1] + bv.y);
            *(float2*)o1 = make_float2(acc[mt][nt][2] + bv.x, acc[mt][nt][3] + bv.y);
        }
    }
}

// ---------------------------------------------------------------------------
extern "C" void kernel_launch(void* const* d_in, const int* in_sizes, int n_in,
                              void* d_out, int out_size) {
    const float* x     = (const float*)d_in[0];
    const float* theta = (const float*)d_in[1];
    const float* W     = (const float*)d_in[2];
    const float* bias  = (const float*)d_in[3];
    float* out = (float*)d_out;

    cudaFuncSetAttribute(out_gemm_mma, cudaFuncAttributeMaxDynamicSharedMemorySize,
                         GSMEM_BYTES);

    qattn_tc<<<TOKENS / 8, 256>>>(x, theta, W);

    dim3 grid(EDIM / 128, TOKENS / 128);   // (4, 128)
    out_gemm_mma<<<grid, 256, GSMEM_BYTES>>>(bias, out);
}

// round 9
// speedup vs baseline: 9.7626x; 1.0187x over previous
#include <cuda_runtime.h>
#include <cuda_bf16.h>
#include <math_constants.h>

#define TOKENS (8 * 2048)
#define EDIM   512
#define NHEAD  64
#define DK     8

// Split-bf16 operands:  value = hi + lo  (each bf16, stored as ushort)
__device__ unsigned short g_Ah[(size_t)TOKENS * EDIM];
__device__ unsigned short g_Al[(size_t)TOKENS * EDIM];
__device__ unsigned short g_Bh[(size_t)EDIM * EDIM];
__device__ unsigned short g_Bl[(size_t)EDIM * EDIM];

// ---- helpers --------------------------------------------------------------
__device__ __forceinline__ float ex2(float x) {
    float y; asm("ex2.approx.f32 %0, %1;" : "=f"(y) : "f"(x)); return y;
}
__device__ __forceinline__ float rcpa(float x) {
    float y; asm("rcp.approx.f32 %0, %1;" : "=f"(y) : "f"(x)); return y;
}
__device__ __forceinline__ unsigned prmt_hi(float a, float b) {
    unsigned d;
    asm("prmt.b32 %0, %1, %2, 0x7632;" : "=r"(d) : "r"(__float_as_uint(a)), "r"(__float_as_uint(b)));
    return d;
}
__device__ __forceinline__ unsigned cvtbf2(float hi_, float lo_) {
    unsigned d;
    asm("cvt.rn.bf16x2.f32 %0, %1, %2;" : "=r"(d) : "f"(hi_), "f"(lo_));
    return d;
}
__device__ __forceinline__ float btrunc(float v) {
    return __uint_as_float(__float_as_uint(v) & 0xFFFF0000u);
}
__device__ __forceinline__ void bsplit(float v, unsigned short& h, unsigned short& l) {
    __nv_bfloat16 hb = __float2bfloat16(v);
    h = __bfloat16_as_ushort(hb);
    l = __bfloat16_as_ushort(__float2bfloat16(v - __bfloat162float(hb)));
}
__device__ __forceinline__ unsigned smem_u32(const void* p) {
    unsigned a;
    asm("{ .reg .u64 t; cvta.to.shared.u64 t, %1; cvt.u32.u64 %0, t; }" : "=r"(a) : "l"(p));
    return a;
}
__device__ __forceinline__ void cp16(unsigned dst, const void* src) {
    asm volatile("cp.async.cg.shared.global [%0], [%1], 16;" :: "r"(dst), "l"(src));
}
__device__ __forceinline__ void ldsm_x4(unsigned& r0, unsigned& r1, unsigned& r2,
                                        unsigned& r3, unsigned addr) {
    asm volatile("ldmatrix.sync.aligned.m8n8.x4.shared.b16 {%0,%1,%2,%3}, [%4];"
                 : "=r"(r0), "=r"(r1), "=r"(r2), "=r"(r3) : "r"(addr));
}
__device__ __forceinline__ void ldsm_x2(unsigned& r0, unsigned& r1, unsigned addr) {
    asm volatile("ldmatrix.sync.aligned.m8n8.x2.shared.b16 {%0,%1}, [%2];"
                 : "=r"(r0), "=r"(r1) : "r"(addr));
}
__device__ __forceinline__ void mma_bf16(float* c, const unsigned* a,
                                         unsigned b0, unsigned b1) {
    asm volatile("mma.sync.aligned.m16n8k16.row.col.f32.bf16.bf16.f32 "
                 "{%0,%1,%2,%3}, {%4,%5,%6,%7}, {%8,%9}, {%0,%1,%2,%3};"
                 : "+f"(c[0]), "+f"(c[1]), "+f"(c[2]), "+f"(c[3])
                 : "r"(a[0]), "r"(a[1]), "r"(a[2]), "r"(a[3]), "r"(b0), "r"(b1));
}

#define SWZ64(o) ((o) ^ (((o) >> 3) & 0x30))

// ---------------------------------------------------------------------------
// Kernel A: tensor-core quantum attention (unchanged from R8).
// ---------------------------------------------------------------------------
#define TOK_SZ 4352
#define PH_OFF 0
#define PL_OFF 1024
#define TH_OFF 2048
#define TL_OFF 3200

__global__ __launch_bounds__(256, 2) void qattn_tc(const float* __restrict__ x,
                                                   const float* __restrict__ theta,
                                                   const float* __restrict__ W) {
    __shared__ char sm[8 * TOK_SZ];

    const int tid = threadIdx.x;
    const int wid = tid >> 5;
    const int lid = tid & 31;

    // Folded W split
    if (blockIdx.x < 256) {
        const int idx = blockIdx.x * 256 + tid;
        const float4 w = ((const float4*)W)[idx];
        unsigned short h0, h1, h2, h3, l0, l1, l2, l3;
        bsplit(w.x, h0, l0); bsplit(w.y, h1, l1);
        bsplit(w.z, h2, l2); bsplit(w.w, h3, l3);
        uint2 hu, lu;
        hu.x = (unsigned)h0 | ((unsigned)h1 << 16);
        hu.y = (unsigned)h2 | ((unsigned)h3 << 16);
        lu.x = (unsigned)l0 | ((unsigned)l1 << 16);
        lu.y = (unsigned)l2 | ((unsigned)l3 << 16);
        ((uint2*)g_Bh)[idx] = hu;
        ((uint2*)g_Bl)[idx] = lu;
    }

    const int token = blockIdx.x * 8 + wid;
    const unsigned base = smem_u32(sm) + wid * TOK_SZ;

    float th[8];
    {
        const float4 t0 = ((const float4*)theta)[0];
        const float4 t1 = ((const float4*)theta)[1];
        th[0] = t0.x; th[1] = t0.y; th[2] = t0.z; th[3] = t0.w;
        th[4] = t1.x; th[5] = t1.y; th[6] = t1.z; th[7] = t1.w;
    }

    const float s = 0.7142224053f;   // sqrt((1/sqrt8)*log2e)

    {
        const float* xb = x + (size_t)token * EDIM + lid * 16;
        const float4 v0 = ((const float4*)xb)[0];
        const float4 v1 = ((const float4*)xb)[1];
        const float4 v2 = ((const float4*)xb)[2];
        const float4 v3 = ((const float4*)xb)[3];
        float pa[8], pb[8];
        pa[0] = __cosf(v0.x + th[0]); pa[1] = __cosf(v0.y + th[1]);
        pa[2] = __cosf(v0.z + th[2]); pa[3] = __cosf(v0.w + th[3]);
        pa[4] = __cosf(v1.x + th[4]); pa[5] = __cosf(v1.y + th[5]);
        pa[6] = __cosf(v1.z + th[6]); pa[7] = __cosf(v1.w + th[7]);
        pb[0] = __cosf(v2.x + th[0]); pb[1] = __cosf(v2.y + th[1]);
        pb[2] = __cosf(v2.z + th[2]); pb[3] = __cosf(v2.w + th[3]);
        pb[4] = __cosf(v3.x + th[4]); pb[5] = __cosf(v3.y + th[5]);
        pb[6] = __cosf(v3.z + th[6]); pb[7] = __cosf(v3.w + th[7]);

        #pragma unroll
        for (int d = 0; d < 8; d++) {
            const unsigned hp = prmt_hi(pa[d], pb[d]);
            *(unsigned*)(sm + (base - smem_u32(sm)) + TH_OFF + d * 144 + lid * 4) = hp;
            const float la = pa[d] - btrunc(pa[d]);
            const float lb = pb[d] - btrunc(pb[d]);
            *(unsigned*)(sm + (base - smem_u32(sm)) + TL_OFF + d * 144 + lid * 4) = cvtbf2(lb, la);
        }

        float sa[8], sb2[8];
        #pragma unroll
        for (int i = 0; i < 8; i++) { sa[i] = pa[i] * s; sb2[i] = pb[i] * s; }

        char* smp = sm + (base - smem_u32(sm));
        uint4 hrow, lrow;
        hrow.x = prmt_hi(sa[0], sa[1]); hrow.y = prmt_hi(sa[2], sa[3]);
        hrow.z = prmt_hi(sa[4], sa[5]); hrow.w = prmt_hi(sa[6], sa[7]);
        lrow.x = cvtbf2(sa[1] - btrunc(sa[1]), sa[0] - btrunc(sa[0]));
        lrow.y = cvtbf2(sa[3] - btrunc(sa[3]), sa[2] - btrunc(sa[2]));
        lrow.z = cvtbf2(sa[5] - btrunc(sa[5]), sa[4] - btrunc(sa[4]));
        lrow.w = cvtbf2(sa[7] - btrunc(sa[7]), sa[6] - btrunc(sa[6]));
        *(uint4*)(smp + PH_OFF + (2 * lid) * 16) = hrow;
        *(uint4*)(smp + PL_OFF + (2 * lid) * 16) = lrow;
        hrow.x = prmt_hi(sb2[0], sb2[1]); hrow.y = prmt_hi(sb2[2], sb2[3]);
        hrow.z = prmt_hi(sb2[4], sb2[5]); hrow.w = prmt_hi(sb2[6], sb2[7]);
        lrow.x = cvtbf2(sb2[1] - btrunc(sb2[1]), sb2[0] - btrunc(sb2[0]));
        lrow.y = cvtbf2(sb2[3] - btrunc(sb2[3]), sb2[2] - btrunc(sb2[2]));
        lrow.z = cvtbf2(sb2[5] - btrunc(sb2[5]), sb2[4] - btrunc(sb2[4]));
        lrow.w = cvtbf2(sb2[7] - btrunc(sb2[7]), sb2[6] - btrunc(sb2[6]));
        *(uint4*)(smp + PH_OFF + (2 * lid + 1) * 16) = hrow;
        *(uint4*)(smp + PL_OFF + (2 * lid + 1) * 16) = lrow;
    }
    __syncwarp();

    unsigned bTh[4][2], bTl[4][2];
    #pragma unroll
    for (int t = 0; t < 2; t++) {
        const unsigned addrh = base + TH_OFF + (lid & 7) * 144 + t * 64 + (lid >> 3) * 16;
        const unsigned addrl = base + TL_OFF + (lid & 7) * 144 + t * 64 + (lid >> 3) * 16;
        ldsm_x4(bTh[2 * t][0], bTh[2 * t][1], bTh[2 * t + 1][0], bTh[2 * t + 1][1], addrh);
        ldsm_x4(bTl[2 * t][0], bTl[2 * t][1], bTl[2 * t + 1][0], bTl[2 * t + 1][1], addrl);
    }

    const int bI  = token >> 11;
    const int sbI = token & 2047;
    const size_t rowTail = (size_t)(bI * 2048) + (size_t)(sbI >> 6);
    const int colOff = (sbI & 63) * DK + 2 * (lid & 3);

    #pragma unroll 1
    for (int ms = 0; ms < 4; ms++) {
        unsigned ah4[4] = {0u, 0u, 0u, 0u}, al4[4] = {0u, 0u, 0u, 0u};
        ldsm_x2(ah4[0], ah4[1], base + PH_OFF + (16 * ms + (lid & 15)) * 16);
        ldsm_x2(al4[0], al4[1], base + PL_OFF + (16 * ms + (lid & 15)) * 16);

        unsigned bh[8], bl[8];
        ldsm_x4(bh[0], bh[1], bh[2], bh[3], base + PH_OFF + lid * 16);
        ldsm_x4(bh[4], bh[5], bh[6], bh[7], base + PH_OFF + (lid + 32) * 16);
        ldsm_x4(bl[0], bl[1], bl[2], bl[3], base + PL_OFF + lid * 16);
        ldsm_x4(bl[4], bl[5], bl[6], bl[7], base + PL_OFF + (lid + 32) * 16);

        float c[8][4];
        #pragma unroll
        for (int nt = 0; nt < 8; nt++) {
            c[nt][0] = c[nt][1] = c[nt][2] = c[nt][3] = 0.f;
            mma_bf16(c[nt], ah4, bh[nt], 0u);
            mma_bf16(c[nt], ah4, bl[nt], 0u);
            mma_bf16(c[nt], al4, bh[nt], 0u);
        }

        float sum0 = 0.f, sum1 = 0.f;
        #pragma unroll
        for (int nt = 0; nt < 8; nt++) {
            c[nt][0] = ex2(c[nt][0]); c[nt][1] = ex2(c[nt][1]);
            c[nt][2] = ex2(c[nt][2]); c[nt][3] = ex2(c[nt][3]);
            sum0 += c[nt][0] + c[nt][1];
            sum1 += c[nt][2] + c[nt][3];
        }
        sum0 += __shfl_xor_sync(0xffffffffu, sum0, 1);
        sum0 += __shfl_xor_sync(0xffffffffu, sum0, 2);
        sum1 += __shfl_xor_sync(0xffffffffu, sum1, 1);
        sum1 += __shfl_xor_sync(0xffffffffu, sum1, 2);
        const float inv0 = rcpa(sum0);
        const float inv1 = rcpa(sum1);

        unsigned Eh[4][4], El[4][4];
        #pragma unroll
        for (int kt = 0; kt < 4; kt++) {
            const int n0 = 2 * kt, n1 = 2 * kt + 1;
            Eh[kt][0] = prmt_hi(c[n0][0], c[n0][1]);
            Eh[kt][1] = prmt_hi(c[n0][2], c[n0][3]);
            Eh[kt][2] = prmt_hi(c[n1][0], c[n1][1]);
            Eh[kt][3] = prmt_hi(c[n1][2], c[n1][3]);
            El[kt][0] = cvtbf2(c[n0][1] - btrunc(c[n0][1]), c[n0][0] - btrunc(c[n0][0]));
            El[kt][1] = cvtbf2(c[n0][3] - btrunc(c[n0][3]), c[n0][2] - btrunc(c[n0][2]));
            El[kt][2] = cvtbf2(c[n1][1] - btrunc(c[n1][1]), c[n1][0] - btrunc(c[n1][0]));
            El[kt][3] = cvtbf2(c[n1][3] - btrunc(c[n1][3]), c[n1][2] - btrunc(c[n1][2]));
        }

        float o[4] = {0.f, 0.f, 0.f, 0.f};
        #pragma unroll
        for (int kt = 0; kt < 4; kt++) {
            mma_bf16(o, Eh[kt], bTh[kt][0], bTh[kt][1]);
            mma_bf16(o, Eh[kt], bTl[kt][0], bTl[kt][1]);
            mma_bf16(o, El[kt], bTh[kt][0], bTh[kt][1]);
        }
        o[0] *= inv0; o[1] *= inv0; o[2] *= inv1; o[3] *= inv1;

        const int h0 = 16 * ms + (lid >> 2);
        const size_t off0 = (rowTail + (size_t)(h0 * 32)) * EDIM + colOff;
        const size_t off1 = (rowTail + (size_t)((h0 + 8) * 32)) * EDIM + colOff;
        *(unsigned*)(g_Ah + off0) = prmt_hi(o[0], o[1]);
        *(unsigned*)(g_Al + off0) = cvtbf2(o[1] - btrunc(o[1]), o[0] - btrunc(o[0]));
        *(unsigned*)(g_Ah + off1) = prmt_hi(o[2], o[3]);
        *(unsigned*)(g_Al + off1) = cvtbf2(o[3] - btrunc(o[3]), o[2] - btrunc(o[2]));
    }
}

// ---------------------------------------------------------------------------
// Kernel B: split-bf16 GEMM, 3-stage cp.async pipeline, 4 warps / 128 threads,
// warp tile 64x64 (2x2 warp grid) -> mma/ldsm ratio 6 (was 4): crossbar no
// longer co-limits the tensor pipe.
// ---------------------------------------------------------------------------
#define TILE_B   8192
#define STAGE_B  32768
#define NSTAGE   3
#define NCHUNK   16
#define GSMEM_BYTES (NSTAGE * STAGE_B)
#define AH_T 0
#define AL_T 1
#define BH_T 2
#define BL_T 3

__device__ __forceinline__ void load_chunk(unsigned sb, int stage, int c,
                                           int rowBase, int colBase, int tid) {
    const unsigned base = sb + stage * STAGE_B;
    #pragma unroll
    for (int i = 0; i < 16; i++) {
        const int v    = i * 128 + tid;   // 0..2047
        const int tile = v >> 9;          // 512 v16 per tile (constant per i)
        const int rem  = v & 511;
        const int r    = rem >> 2;
        const int c16  = rem & 3;
        const unsigned short* src;
        if      (tile == 0) src = g_Ah + (size_t)(rowBase + r) * EDIM;
        else if (tile == 1) src = g_Al + (size_t)(rowBase + r) * EDIM;
        else if (tile == 2) src = g_Bh + (size_t)(colBase + r) * EDIM;
        else                src = g_Bl + (size_t)(colBase + r) * EDIM;
        src += c * 32 + c16 * 8;
        cp16(base + tile * TILE_B + SWZ64(r * 64 + c16 * 16), src);
    }
    asm volatile("cp.async.commit_group;" ::: "memory");
}

__global__ __launch_bounds__(128, 2) void out_gemm_mma(const float* __restrict__ bias,
                                                       float* __restrict__ out) {
    extern __shared__ char smem[];
    const unsigned sb = smem_u32(smem);
    const int tid = threadIdx.x;
    const int wid = tid >> 5;
    const int lid = tid & 31;

    const int rowBase = blockIdx.y * 128;
    const int colBase = blockIdx.x * 128;

    const int wy = wid & 1;    // m: 64 rows
    const int wx = wid >> 1;   // n: 64 cols

    const int lr  = lid & 7;
    const int sub = lid >> 3;

    float acc[4][8][4];
    #pragma unroll
    for (int mt = 0; mt < 4; mt++)
        #pragma unroll
        for (int nt = 0; nt < 8; nt++)
            #pragma unroll
            for (int q = 0; q < 4; q++) acc[mt][nt][q] = 0.f;

    load_chunk(sb, 0, 0, rowBase, colBase, tid);
    load_chunk(sb, 1, 1, rowBase, colBase, tid);

    int stage = 0;
    for (int c = 0; c < NCHUNK; c++) {
        if (c < NCHUNK - 1) {
            asm volatile("cp.async.wait_group 1;" ::: "memory");
        } else {
            asm volatile("cp.async.wait_group 0;" ::: "memory");
        }
        __syncthreads();

        const unsigned stg = sb + (unsigned)stage * STAGE_B;

        #pragma unroll
        for (int kk = 0; kk < 2; kk++) {
            const int kb = kk * 32;

            // A frags for 64 rows (4 m16 tiles), hi + lo
            unsigned ah[4][4], al[4][4];
            #pragma unroll
            for (int mt = 0; mt < 4; mt++) {
                const int rowA = wy * 64 + mt * 16 + lr + (sub & 1) * 8;
                const int colb = kb + (sub >> 1) * 16;
                const unsigned off = SWZ64(rowA * 64 + colb);
                ldsm_x4(ah[mt][0], ah[mt][1], ah[mt][2], ah[mt][3], stg + AH_T * TILE_B + off);
                ldsm_x4(al[mt][0], al[mt][1], al[mt][2], al[mt][3], stg + AL_T * TILE_B + off);
            }

            // B frags for 64 cols (4 n16 tiles), hi + lo
            unsigned bh[4][4], bl[4][4];
            #pragma unroll
            for (int nt16 = 0; nt16 < 4; nt16++) {
                const int rowB = wx * 64 + nt16 * 16 + lr + (sub >> 1) * 8;
                const int colb = kb + (sub & 1) * 16;
                const unsigned off = SWZ64(rowB * 64 + colb);
                ldsm_x4(bh[nt16][0], bh[nt16][1], bh[nt16][2], bh[nt16][3], stg + BH_T * TILE_B + off);
                ldsm_x4(bl[nt16][0], bl[nt16][1], bl[nt16][2], bl[nt16][3], stg + BL_T * TILE_B + off);
            }

            // term-major issue: same-acc mmas are 32 apart (no dep stalls)
            #pragma unroll
            for (int nt16 = 0; nt16 < 4; nt16++)
                #pragma unroll
                for (int mt = 0; mt < 4; mt++) {
                    mma_bf16(acc[mt][nt16 * 2],     ah[mt], bh[nt16][0], bh[nt16][1]);
                    mma_bf16(acc[mt][nt16 * 2 + 1], ah[mt], bh[nt16][2], bh[nt16][3]);
                }
            #pragma unroll
            for (int nt16 = 0; nt16 < 4; nt16++)
                #pragma unroll
                for (int mt = 0; mt < 4; mt++) {
                    mma_bf16(acc[mt][nt16 * 2],     ah[mt], bl[nt16][0], bl[nt16][1]);
                    mma_bf16(acc[mt][nt16 * 2 + 1], ah[mt], bl[nt16][2], bl[nt16][3]);
                }
            #pragma unroll
            for (int nt16 = 0; nt16 < 4; nt16++)
                #pragma unroll
                for (int mt = 0; mt < 4; mt++) {
                    mma_bf16(acc[mt][nt16 * 2],     al[mt], bh[nt16][0], bh[nt16][1]);
                    mma_bf16(acc[mt][nt16 * 2 + 1], al[mt], bh[nt16][2], bh[nt16][3]);
                }
        }

        if (c + 2 < NCHUNK) {
            int fs = stage + 2;
            if (fs >= NSTAGE) fs -= NSTAGE;
            load_chunk(sb, fs, c + 2, rowBase, colBase, tid);
        }
        if (++stage == NSTAGE) stage = 0;
    }

    // epilogue: bias + store
    const int qrow = lid >> 2;
    const int qcol = (lid & 3) * 2;
    #pragma unroll
    for (int mt = 0; mt < 4; mt++) {
        #pragma unroll
        for (int nt = 0; nt < 8; nt++) {
            const int row = rowBase + wy * 64 + mt * 16 + qrow;
            const int col = colBase + wx * 64 + nt * 8 + qcol;
            const float2 bv = *(const float2*)&bias[col];
            float* o0 = out + (size_t)row * EDIM + col;
            float* o1 = o0 + 8 * EDIM;
            *(float2*)o0 = make_float2(acc[mt][nt][0] + bv.x, acc[mt][nt][1] + bv.y);
            *(float2*)o1 = make_float2(acc[mt][nt][2] + bv.x, acc[mt][nt][3] + bv.y);
        }
    }
}

// ---------------------------------------------------------------------------
extern "C" void kernel_launch(void* const* d_in, const int* in_sizes, int n_in,
                              void* d_out, int out_size) {
    const float* x     = (const float*)d_in[0];
    const float* theta = (const float*)d_in[1];
    const float* W     = (const float*)d_in[2];
    const float* bias  = (const float*)d_in[3];
    float* out = (float*)d_out;

    cudaFuncSetAttribute(out_gemm_mma, cudaFuncAttributeMaxDynamicSharedMemorySize,
                         GSMEM_BYTES);

    qattn_tc<<<TOKENS / 8, 256>>>(x, theta, W);

    dim3 grid(EDIM / 128, TOKENS / 128);   // (4, 128)
    out_gemm_mma<<<grid, 128, GSMEM_BYTES>>>(bias, out);
}

// round 10
// speedup vs baseline: 15.1007x; 1.5468x over previous
#include <cuda_runtime.h>
#include <cuda_bf16.h>
#include <math_constants.h>

#define TOKENS (8 * 2048)
#define EDIM   512
#define NHEAD  64
#define DK     8

// fp16 operands for the output GEMM (1-term: fp16 quantization 2^-12 is enough)
__device__ unsigned short g_A[(size_t)TOKENS * EDIM];   // mid, fp16
__device__ unsigned short g_B[(size_t)EDIM * EDIM];     // W,  fp16

// ---- helpers --------------------------------------------------------------
__device__ __forceinline__ float ex2(float x) {
    float y; asm("ex2.approx.f32 %0, %1;" : "=f"(y) : "f"(x)); return y;
}
__device__ __forceinline__ float rcpa(float x) {
    float y; asm("rcp.approx.f32 %0, %1;" : "=f"(y) : "f"(x)); return y;
}
__device__ __forceinline__ unsigned prmt_hi(float a, float b) {
    unsigned d;
    asm("prmt.b32 %0, %1, %2, 0x7632;" : "=r"(d) : "r"(__float_as_uint(a)), "r"(__float_as_uint(b)));
    return d;
}
__device__ __forceinline__ unsigned cvtbf2(float hi_, float lo_) {
    unsigned d;
    asm("cvt.rn.bf16x2.f32 %0, %1, %2;" : "=r"(d) : "f"(hi_), "f"(lo_));
    return d;
}
__device__ __forceinline__ unsigned cvtf16x2(float hi_, float lo_) {
    unsigned d;
    asm("cvt.rn.f16x2.f32 %0, %1, %2;" : "=r"(d) : "f"(hi_), "f"(lo_));
    return d;
}
__device__ __forceinline__ float btrunc(float v) {
    return __uint_as_float(__float_as_uint(v) & 0xFFFF0000u);
}
__device__ __forceinline__ unsigned smem_u32(const void* p) {
    unsigned a;
    asm("{ .reg .u64 t; cvta.to.shared.u64 t, %1; cvt.u32.u64 %0, t; }" : "=r"(a) : "l"(p));
    return a;
}
__device__ __forceinline__ void cp16(unsigned dst, const void* src) {
    asm volatile("cp.async.cg.shared.global [%0], [%1], 16;" :: "r"(dst), "l"(src));
}
__device__ __forceinline__ void ldsm_x4(unsigned& r0, unsigned& r1, unsigned& r2,
                                        unsigned& r3, unsigned addr) {
    asm volatile("ldmatrix.sync.aligned.m8n8.x4.shared.b16 {%0,%1,%2,%3}, [%4];"
                 : "=r"(r0), "=r"(r1), "=r"(r2), "=r"(r3) : "r"(addr));
}
__device__ __forceinline__ void ldsm_x2(unsigned& r0, unsigned& r1, unsigned addr) {
    asm volatile("ldmatrix.sync.aligned.m8n8.x2.shared.b16 {%0,%1}, [%2];"
                 : "=r"(r0), "=r"(r1) : "r"(addr));
}
__device__ __forceinline__ void mma_bf16(float* c, const unsigned* a,
                                         unsigned b0, unsigned b1) {
    asm volatile("mma.sync.aligned.m16n8k16.row.col.f32.bf16.bf16.f32 "
                 "{%0,%1,%2,%3}, {%4,%5,%6,%7}, {%8,%9}, {%0,%1,%2,%3};"
                 : "+f"(c[0]), "+f"(c[1]), "+f"(c[2]), "+f"(c[3])
                 : "r"(a[0]), "r"(a[1]), "r"(a[2]), "r"(a[3]), "r"(b0), "r"(b1));
}
__device__ __forceinline__ void mma_f16(float* c, const unsigned* a,
                                        unsigned b0, unsigned b1) {
    asm volatile("mma.sync.aligned.m16n8k16.row.col.f32.f16.f16.f32 "
                 "{%0,%1,%2,%3}, {%4,%5,%6,%7}, {%8,%9}, {%0,%1,%2,%3};"
                 : "+f"(c[0]), "+f"(c[1]), "+f"(c[2]), "+f"(c[3])
                 : "r"(a[0]), "r"(a[1]), "r"(a[2]), "r"(a[3]), "r"(b0), "r"(b1));
}

#define SWZ64(o) ((o) ^ (((o) >> 3) & 0x30))

// ---------------------------------------------------------------------------
// Kernel A: tensor-core quantum attention (R8 internals, bf16 3-term).
// Epilogue now writes SINGLE fp16 mid (g_A) + W folded to fp16 (g_B).
// ---------------------------------------------------------------------------
#define TOK_SZ 4352
#define PH_OFF 0
#define PL_OFF 1024
#define TH_OFF 2048
#define TL_OFF 3200

__global__ __launch_bounds__(256, 2) void qattn_tc(const float* __restrict__ x,
                                                   const float* __restrict__ theta,
                                                   const float* __restrict__ W) {
    __shared__ char sm[8 * TOK_SZ];

    const int tid = threadIdx.x;
    const int wid = tid >> 5;
    const int lid = tid & 31;

    // Folded W conversion to fp16
    if (blockIdx.x < 256) {
        const int idx = blockIdx.x * 256 + tid;
        const float4 w = ((const float4*)W)[idx];
        uint2 hu;
        hu.x = cvtf16x2(w.y, w.x);
        hu.y = cvtf16x2(w.w, w.z);
        ((uint2*)g_B)[idx] = hu;
    }

    const int token = blockIdx.x * 8 + wid;
    const unsigned base = smem_u32(sm) + wid * TOK_SZ;

    float th[8];
    {
        const float4 t0 = ((const float4*)theta)[0];
        const float4 t1 = ((const float4*)theta)[1];
        th[0] = t0.x; th[1] = t0.y; th[2] = t0.z; th[3] = t0.w;
        th[4] = t1.x; th[5] = t1.y; th[6] = t1.z; th[7] = t1.w;
    }

    const float s = 0.7142224053f;   // sqrt((1/sqrt8)*log2e)

    {
        const float* xb = x + (size_t)token * EDIM + lid * 16;
        const float4 v0 = ((const float4*)xb)[0];
        const float4 v1 = ((const float4*)xb)[1];
        const float4 v2 = ((const float4*)xb)[2];
        const float4 v3 = ((const float4*)xb)[3];
        float pa[8], pb[8];
        pa[0] = __cosf(v0.x + th[0]); pa[1] = __cosf(v0.y + th[1]);
        pa[2] = __cosf(v0.z + th[2]); pa[3] = __cosf(v0.w + th[3]);
        pa[4] = __cosf(v1.x + th[4]); pa[5] = __cosf(v1.y + th[5]);
        pa[6] = __cosf(v1.z + th[6]); pa[7] = __cosf(v1.w + th[7]);
        pb[0] = __cosf(v2.x + th[0]); pb[1] = __cosf(v2.y + th[1]);
        pb[2] = __cosf(v2.z + th[2]); pb[3] = __cosf(v2.w + th[3]);
        pb[4] = __cosf(v3.x + th[4]); pb[5] = __cosf(v3.y + th[5]);
        pb[6] = __cosf(v3.z + th[6]); pb[7] = __cosf(v3.w + th[7]);

        #pragma unroll
        for (int d = 0; d < 8; d++) {
            const unsigned hp = prmt_hi(pa[d], pb[d]);
            *(unsigned*)(sm + (base - smem_u32(sm)) + TH_OFF + d * 144 + lid * 4) = hp;
            const float la = pa[d] - btrunc(pa[d]);
            const float lb = pb[d] - btrunc(pb[d]);
            *(unsigned*)(sm + (base - smem_u32(sm)) + TL_OFF + d * 144 + lid * 4) = cvtbf2(lb, la);
        }

        float sa[8], sb2[8];
        #pragma unroll
        for (int i = 0; i < 8; i++) { sa[i] = pa[i] * s; sb2[i] = pb[i] * s; }

        char* smp = sm + (base - smem_u32(sm));
        uint4 hrow, lrow;
        hrow.x = prmt_hi(sa[0], sa[1]); hrow.y = prmt_hi(sa[2], sa[3]);
        hrow.z = prmt_hi(sa[4], sa[5]); hrow.w = prmt_hi(sa[6], sa[7]);
        lrow.x = cvtbf2(sa[1] - btrunc(sa[1]), sa[0] - btrunc(sa[0]));
        lrow.y = cvtbf2(sa[3] - btrunc(sa[3]), sa[2] - btrunc(sa[2]));
        lrow.z = cvtbf2(sa[5] - btrunc(sa[5]), sa[4] - btrunc(sa[4]));
        lrow.w = cvtbf2(sa[7] - btrunc(sa[7]), sa[6] - btrunc(sa[6]));
        *(uint4*)(smp + PH_OFF + (2 * lid) * 16) = hrow;
        *(uint4*)(smp + PL_OFF + (2 * lid) * 16) = lrow;
        hrow.x = prmt_hi(sb2[0], sb2[1]); hrow.y = prmt_hi(sb2[2], sb2[3]);
        hrow.z = prmt_hi(sb2[4], sb2[5]); hrow.w = prmt_hi(sb2[6], sb2[7]);
        lrow.x = cvtbf2(sb2[1] - btrunc(sb2[1]), sb2[0] - btrunc(sb2[0]));
        lrow.y = cvtbf2(sb2[3] - btrunc(sb2[3]), sb2[2] - btrunc(sb2[2]));
        lrow.z = cvtbf2(sb2[5] - btrunc(sb2[5]), sb2[4] - btrunc(sb2[4]));
        lrow.w = cvtbf2(sb2[7] - btrunc(sb2[7]), sb2[6] - btrunc(sb2[6]));
        *(uint4*)(smp + PH_OFF + (2 * lid + 1) * 16) = hrow;
        *(uint4*)(smp + PL_OFF + (2 * lid + 1) * 16) = lrow;
    }
    __syncwarp();

    unsigned bTh[4][2], bTl[4][2];
    #pragma unroll
    for (int t = 0; t < 2; t++) {
        const unsigned addrh = base + TH_OFF + (lid & 7) * 144 + t * 64 + (lid >> 3) * 16;
        const unsigned addrl = base + TL_OFF + (lid & 7) * 144 + t * 64 + (lid >> 3) * 16;
        ldsm_x4(bTh[2 * t][0], bTh[2 * t][1], bTh[2 * t + 1][0], bTh[2 * t + 1][1], addrh);
        ldsm_x4(bTl[2 * t][0], bTl[2 * t][1], bTl[2 * t + 1][0], bTl[2 * t + 1][1], addrl);
    }

    const int bI  = token >> 11;
    const int sbI = token & 2047;
    const size_t rowTail = (size_t)(bI * 2048) + (size_t)(sbI >> 6);
    const int colOff = (sbI & 63) * DK + 2 * (lid & 3);

    #pragma unroll 1
    for (int ms = 0; ms < 4; ms++) {
        unsigned ah4[4] = {0u, 0u, 0u, 0u}, al4[4] = {0u, 0u, 0u, 0u};
        ldsm_x2(ah4[0], ah4[1], base + PH_OFF + (16 * ms + (lid & 15)) * 16);
        ldsm_x2(al4[0], al4[1], base + PL_OFF + (16 * ms + (lid & 15)) * 16);

        unsigned bh[8], bl[8];
        ldsm_x4(bh[0], bh[1], bh[2], bh[3], base + PH_OFF + lid * 16);
        ldsm_x4(bh[4], bh[5], bh[6], bh[7], base + PH_OFF + (lid + 32) * 16);
        ldsm_x4(bl[0], bl[1], bl[2], bl[3], base + PL_OFF + lid * 16);
        ldsm_x4(bl[4], bl[5], bl[6], bl[7], base + PL_OFF + (lid + 32) * 16);

        float c[8][4];
        #pragma unroll
        for (int nt = 0; nt < 8; nt++) {
            c[nt][0] = c[nt][1] = c[nt][2] = c[nt][3] = 0.f;
            mma_bf16(c[nt], ah4, bh[nt], 0u);
            mma_bf16(c[nt], ah4, bl[nt], 0u);
            mma_bf16(c[nt], al4, bh[nt], 0u);
        }

        float sum0 = 0.f, sum1 = 0.f;
        #pragma unroll
        for (int nt = 0; nt < 8; nt++) {
            c[nt][0] = ex2(c[nt][0]); c[nt][1] = ex2(c[nt][1]);
            c[nt][2] = ex2(c[nt][2]); c[nt][3] = ex2(c[nt][3]);
            sum0 += c[nt][0] + c[nt][1];
            sum1 += c[nt][2] + c[nt][3];
        }
        sum0 += __shfl_xor_sync(0xffffffffu, sum0, 1);
        sum0 += __shfl_xor_sync(0xffffffffu, sum0, 2);
        sum1 += __shfl_xor_sync(0xffffffffu, sum1, 1);
        sum1 += __shfl_xor_sync(0xffffffffu, sum1, 2);
        const float inv0 = rcpa(sum0);
        const float inv1 = rcpa(sum1);

        unsigned Eh[4][4], El[4][4];
        #pragma unroll
        for (int kt = 0; kt < 4; kt++) {
            const int n0 = 2 * kt, n1 = 2 * kt + 1;
            Eh[kt][0] = prmt_hi(c[n0][0], c[n0][1]);
            Eh[kt][1] = prmt_hi(c[n0][2], c[n0][3]);
            Eh[kt][2] = prmt_hi(c[n1][0], c[n1][1]);
            Eh[kt][3] = prmt_hi(c[n1][2], c[n1][3]);
            El[kt][0] = cvtbf2(c[n0][1] - btrunc(c[n0][1]), c[n0][0] - btrunc(c[n0][0]));
            El[kt][1] = cvtbf2(c[n0][3] - btrunc(c[n0][3]), c[n0][2] - btrunc(c[n0][2]));
            El[kt][2] = cvtbf2(c[n1][1] - btrunc(c[n1][1]), c[n1][0] - btrunc(c[n1][0]));
            El[kt][3] = cvtbf2(c[n1][3] - btrunc(c[n1][3]), c[n1][2] - btrunc(c[n1][2]));
        }

        float o[4] = {0.f, 0.f, 0.f, 0.f};
        #pragma unroll
        for (int kt = 0; kt < 4; kt++) {
            mma_bf16(o, Eh[kt], bTh[kt][0], bTh[kt][1]);
            mma_bf16(o, Eh[kt], bTl[kt][0], bTl[kt][1]);
            mma_bf16(o, El[kt], bTh[kt][0], bTh[kt][1]);
        }
        o[0] *= inv0; o[1] *= inv0; o[2] *= inv1; o[3] *= inv1;

        // single fp16 store of mid (permuted layout)
        const int h0 = 16 * ms + (lid >> 2);
        const size_t off0 = (rowTail + (size_t)(h0 * 32)) * EDIM + colOff;
        const size_t off1 = (rowTail + (size_t)((h0 + 8) * 32)) * EDIM + colOff;
        *(unsigned*)(g_A + off0) = cvtf16x2(o[1], o[0]);
        *(unsigned*)(g_A + off1) = cvtf16x2(o[3], o[2]);
    }
}

// ---------------------------------------------------------------------------
// Kernel B: 1-term fp16 GEMM on mma.sync, 3-stage cp.async pipeline.
// out[16384,512] = A_fp16 @ B_fp16^T + bias   (err ~2e-4 << 1e-3)
// CTA 128x128, K-chunks of 32; 2 tiles/stage (A, B; 8KB each, SW64).
// 8 warps in 4(m) x 2(n); warp tile 32x64.
// ---------------------------------------------------------------------------
#define TILE_B   8192
#define STAGE_B  16384
#define NSTAGE   3
#define NCHUNK   16
#define GSMEM_BYTES (NSTAGE * STAGE_B)
#define A_T 0
#define B_T 1

__device__ __forceinline__ void load_chunk(unsigned sb, int stage, int c,
                                           int rowBase, int colBase, int tid) {
    const unsigned base = sb + stage * STAGE_B;
    #pragma unroll
    for (int i = 0; i < 4; i++) {
        const int v    = i * 256 + tid;   // 0..1023
        const int tile = v >> 9;          // 512 v16 per tile (constant per i)
        const int rem  = v & 511;
        const int r    = rem >> 2;
        const int c16  = rem & 3;
        const unsigned short* src;
        if (tile == 0) src = g_A + (size_t)(rowBase + r) * EDIM;
        else           src = g_B + (size_t)(colBase + r) * EDIM;
        src += c * 32 + c16 * 8;
        cp16(base + tile * TILE_B + SWZ64(r * 64 + c16 * 16), src);
    }
    asm volatile("cp.async.commit_group;" ::: "memory");
}

__global__ __launch_bounds__(256, 2) void out_gemm_mma(const float* __restrict__ bias,
                                                       float* __restrict__ out) {
    extern __shared__ char smem[];
    const unsigned sb = smem_u32(smem);
    const int tid = threadIdx.x;
    const int wid = tid >> 5;
    const int lid = tid & 31;

    const int rowBase = blockIdx.y * 128;
    const int colBase = blockIdx.x * 128;

    const int wy = wid & 3;    // m: 32 rows each
    const int wx = wid >> 2;   // n: 64 cols each

    const int lr  = lid & 7;
    const int sub = lid >> 3;

    float acc[2][8][4];
    #pragma unroll
    for (int mt = 0; mt < 2; mt++)
        #pragma unroll
        for (int nt = 0; nt < 8; nt++)
            #pragma unroll
            for (int q = 0; q < 4; q++) acc[mt][nt][q] = 0.f;

    load_chunk(sb, 0, 0, rowBase, colBase, tid);
    load_chunk(sb, 1, 1, rowBase, colBase, tid);

    int stage = 0;
    for (int c = 0; c < NCHUNK; c++) {
        if (c < NCHUNK - 1) {
            asm volatile("cp.async.wait_group 1;" ::: "memory");
        } else {
            asm volatile("cp.async.wait_group 0;" ::: "memory");
        }
        __syncthreads();

        const unsigned stg = sb + (unsigned)stage * STAGE_B;

        #pragma unroll
        for (int kk = 0; kk < 2; kk++) {
            const int kb = kk * 32;

            unsigned ah[2][4];
            #pragma unroll
            for (int mt = 0; mt < 2; mt++) {
                const int rowA = wy * 32 + mt * 16 + lr + (sub & 1) * 8;
                const int colb = kb + (sub >> 1) * 16;
                const unsigned off = SWZ64(rowA * 64 + colb);
                ldsm_x4(ah[mt][0], ah[mt][1], ah[mt][2], ah[mt][3], stg + A_T * TILE_B + off);
            }

            unsigned bh[4][4];
            #pragma unroll
            for (int nt16 = 0; nt16 < 4; nt16++) {
                const int rowB = wx * 64 + nt16 * 16 + lr + (sub >> 1) * 8;
                const int colb = kb + (sub & 1) * 16;
                const unsigned off = SWZ64(rowB * 64 + colb);
                ldsm_x4(bh[nt16][0], bh[nt16][1], bh[nt16][2], bh[nt16][3], stg + B_T * TILE_B + off);
            }

            #pragma unroll
            for (int nt16 = 0; nt16 < 4; nt16++)
                #pragma unroll
                for (int mt = 0; mt < 2; mt++) {
                    mma_f16(acc[mt][nt16 * 2],     ah[mt], bh[nt16][0], bh[nt16][1]);
                    mma_f16(acc[mt][nt16 * 2 + 1], ah[mt], bh[nt16][2], bh[nt16][3]);
                }
        }

        if (c + 2 < NCHUNK) {
            int fs = stage + 2;
            if (fs >= NSTAGE) fs -= NSTAGE;
            load_chunk(sb, fs, c + 2, rowBase, colBase, tid);
        }
        if (++stage == NSTAGE) stage = 0;
    }

    // epilogue: bias + store
    const int qrow = lid >> 2;
    const int qcol = (lid & 3) * 2;
    #pragma unroll
    for (int mt = 0; mt < 2; mt++) {
        #pragma unroll
        for (int nt = 0; nt < 8; nt++) {
            const int row = rowBase + wy * 32 + mt * 16 + qrow;
            const int col = colBase + wx * 64 + nt * 8 + qcol;
            const float2 bv = *(const float2*)&bias[col];
            float* o0 = out + (size_t)row * EDIM + col;
            float* o1 = o0 + 8 * EDIM;
            *(float2*)o0 = make_float2(acc[mt][nt][0] + bv.x, acc[mt][nt][1] + bv.y);
            *(float2*)o1 = make_float2(acc[mt][nt][2] + bv.x, acc[mt][nt][3] + bv.y);
        }
    }
}

// ---------------------------------------------------------------------------
extern "C" void kernel_launch(void* const* d_in, const int* in_sizes, int n_in,
                              void* d_out, int out_size) {
    const float* x     = (const float*)d_in[0];
    const float* theta = (const float*)d_in[1];
    const float* W     = (const float*)d_in[2];
    const float* bias  = (const float*)d_in[3];
    float* out = (float*)d_out;

    cudaFuncSetAttribute(out_gemm_mma, cudaFuncAttributeMaxDynamicSharedMemorySize,
                         GSMEM_BYTES);

    qattn_tc<<<TOKENS / 8, 256>>>(x, theta, W);

    dim3 grid(EDIM / 128, TOKENS / 128);   // (4, 128)
    out_gemm_mma<<<grid, 256, GSMEM_BYTES>>>(bias, out);
}

// round 11
// speedup vs baseline: 19.3413x; 1.2808x over previous
#include <cuda_runtime.h>
#include <cuda_bf16.h>
#include <math_constants.h>

#define TOKENS (8 * 2048)
#define EDIM   512
#define NHEAD  64
#define DK     8

// fp16 operands for the output GEMM (1-term: fp16 quantization 2^-12 is enough)
__device__ unsigned short g_A[(size_t)TOKENS * EDIM];   // mid, fp16
__device__ unsigned short g_B[(size_t)EDIM * EDIM];     // W,  fp16

// ---- helpers --------------------------------------------------------------
__device__ __forceinline__ float ex2(float x) {
    float y; asm("ex2.approx.f32 %0, %1;" : "=f"(y) : "f"(x)); return y;
}
__device__ __forceinline__ float rcpa(float x) {
    float y; asm("rcp.approx.f32 %0, %1;" : "=f"(y) : "f"(x)); return y;
}
__device__ __forceinline__ unsigned cvtf16x2(float hi_, float lo_) {
    unsigned d;
    asm("cvt.rn.f16x2.f32 %0, %1, %2;" : "=r"(d) : "f"(hi_), "f"(lo_));
    return d;
}
__device__ __forceinline__ unsigned smem_u32(const void* p) {
    unsigned a;
    asm("{ .reg .u64 t; cvta.to.shared.u64 t, %1; cvt.u32.u64 %0, t; }" : "=r"(a) : "l"(p));
    return a;
}
__device__ __forceinline__ void cp16(unsigned dst, const void* src) {
    asm volatile("cp.async.cg.shared.global [%0], [%1], 16;" :: "r"(dst), "l"(src));
}
__device__ __forceinline__ void ldsm_x4(unsigned& r0, unsigned& r1, unsigned& r2,
                                        unsigned& r3, unsigned addr) {
    asm volatile("ldmatrix.sync.aligned.m8n8.x4.shared.b16 {%0,%1,%2,%3}, [%4];"
                 : "=r"(r0), "=r"(r1), "=r"(r2), "=r"(r3) : "r"(addr));
}
__device__ __forceinline__ void ldsm_x2(unsigned& r0, unsigned& r1, unsigned addr) {
    asm volatile("ldmatrix.sync.aligned.m8n8.x2.shared.b16 {%0,%1}, [%2];"
                 : "=r"(r0), "=r"(r1) : "r"(addr));
}
__device__ __forceinline__ void mma_f16(float* c, const unsigned* a,
                                        unsigned b0, unsigned b1) {
    asm volatile("mma.sync.aligned.m16n8k16.row.col.f32.f16.f16.f32 "
                 "{%0,%1,%2,%3}, {%4,%5,%6,%7}, {%8,%9}, {%0,%1,%2,%3};"
                 : "+f"(c[0]), "+f"(c[1]), "+f"(c[2]), "+f"(c[3])
                 : "r"(a[0]), "r"(a[1]), "r"(a[2]), "r"(a[3]), "r"(b0), "r"(b1));
}

#define SWZ64(o) ((o) ^ (((o) >> 3) & 0x30))

// ---------------------------------------------------------------------------
// Kernel A: tensor-core quantum attention, ALL-fp16 1-term.
// Per-token smem (warp-private):
//   PH: P scaled by s=sqrt((1/sqrt8)*log2e), g-major: 64 x 8 fp16 (16B rows)
//   TH: P raw, d-major: 8 x 64 fp16 (144B padded rows, conflict-free)
// S = (sP)(sP)^T -> ex2 = exp(score/sqrt8); attn = E @ T; single fp16 mid out.
// Blocks 0..255 also fold W to fp16.
// ---------------------------------------------------------------------------
#define TOK_SZ 2304
#define PH_OFF 0
#define TH_OFF 1024

__global__ __launch_bounds__(256, 2) void qattn_tc(const float* __restrict__ x,
                                                   const float* __restrict__ theta,
                                                   const float* __restrict__ W) {
    __shared__ char sm[8 * TOK_SZ];

    const int tid = threadIdx.x;
    const int wid = tid >> 5;
    const int lid = tid & 31;

    // Folded W conversion to fp16
    if (blockIdx.x < 256) {
        const int idx = blockIdx.x * 256 + tid;
        const float4 w = ((const float4*)W)[idx];
        uint2 hu;
        hu.x = cvtf16x2(w.y, w.x);
        hu.y = cvtf16x2(w.w, w.z);
        ((uint2*)g_B)[idx] = hu;
    }

    const int token = blockIdx.x * 8 + wid;
    const unsigned base = smem_u32(sm) + wid * TOK_SZ;
    char* smp = sm + wid * TOK_SZ;

    float th[8];
    {
        const float4 t0 = ((const float4*)theta)[0];
        const float4 t1 = ((const float4*)theta)[1];
        th[0] = t0.x; th[1] = t0.y; th[2] = t0.z; th[3] = t0.w;
        th[4] = t1.x; th[5] = t1.y; th[6] = t1.z; th[7] = t1.w;
    }

    const float s = 0.7142224053f;   // sqrt((1/sqrt8)*log2e)

    // ---- P generation: lane handles rows g=2*lid and 2*lid+1 --------------
    {
        const float* xb = x + (size_t)token * EDIM + lid * 16;
        const float4 v0 = ((const float4*)xb)[0];
        const float4 v1 = ((const float4*)xb)[1];
        const float4 v2 = ((const float4*)xb)[2];
        const float4 v3 = ((const float4*)xb)[3];
        float pa[8], pb[8];
        pa[0] = __cosf(v0.x + th[0]); pa[1] = __cosf(v0.y + th[1]);
        pa[2] = __cosf(v0.z + th[2]); pa[3] = __cosf(v0.w + th[3]);
        pa[4] = __cosf(v1.x + th[4]); pa[5] = __cosf(v1.y + th[5]);
        pa[6] = __cosf(v1.z + th[6]); pa[7] = __cosf(v1.w + th[7]);
        pb[0] = __cosf(v2.x + th[0]); pb[1] = __cosf(v2.y + th[1]);
        pb[2] = __cosf(v2.z + th[2]); pb[3] = __cosf(v2.w + th[3]);
        pb[4] = __cosf(v3.x + th[4]); pb[5] = __cosf(v3.y + th[5]);
        pb[6] = __cosf(v3.z + th[6]); pb[7] = __cosf(v3.w + th[7]);

        // T (raw, d-major fp16): row d, col pair (2*lid, 2*lid+1)
        #pragma unroll
        for (int d = 0; d < 8; d++) {
            *(unsigned*)(smp + TH_OFF + d * 144 + lid * 4) = cvtf16x2(pb[d], pa[d]);
        }

        // PH (g-major, scaled fp16): rows 2*lid, 2*lid+1, 8 fp16 = 16B each
        uint4 row;
        row.x = cvtf16x2(pa[1] * s, pa[0] * s);
        row.y = cvtf16x2(pa[3] * s, pa[2] * s);
        row.z = cvtf16x2(pa[5] * s, pa[4] * s);
        row.w = cvtf16x2(pa[7] * s, pa[6] * s);
        *(uint4*)(smp + PH_OFF + (2 * lid) * 16) = row;
        row.x = cvtf16x2(pb[1] * s, pb[0] * s);
        row.y = cvtf16x2(pb[3] * s, pb[2] * s);
        row.z = cvtf16x2(pb[5] * s, pb[4] * s);
        row.w = cvtf16x2(pb[7] * s, pb[6] * s);
        *(uint4*)(smp + PH_OFF + (2 * lid + 1) * 16) = row;
    }
    __syncwarp();

    // ---- hoisted A-stage B-frags from T (invariant across slices) ---------
    unsigned bT[4][2];
    #pragma unroll
    for (int t = 0; t < 2; t++) {
        const unsigned addrh = base + TH_OFF + (lid & 7) * 144 + t * 64 + (lid >> 3) * 16;
        ldsm_x4(bT[2 * t][0], bT[2 * t][1], bT[2 * t + 1][0], bT[2 * t + 1][1], addrh);
    }

    const int bI  = token >> 11;
    const int sbI = token & 2047;
    const size_t rowTail = (size_t)(bI * 2048) + (size_t)(sbI >> 6);
    const int colOff = (sbI & 63) * DK + 2 * (lid & 3);

    // ---- slice loop: 4 x (16 rows of S + softmax + attn) ------------------
    #pragma unroll 1
    for (int ms = 0; ms < 4; ms++) {
        // A-frags of scaled P (k16, upper k zero)
        unsigned ah4[4] = {0u, 0u, 0u, 0u};
        ldsm_x2(ah4[0], ah4[1], base + PH_OFF + (16 * ms + (lid & 15)) * 16);

        // B-frags: all 64 g-rows of scaled P (8 n8-tiles)
        unsigned bh[8];
        ldsm_x4(bh[0], bh[1], bh[2], bh[3], base + PH_OFF + lid * 16);
        ldsm_x4(bh[4], bh[5], bh[6], bh[7], base + PH_OFF + (lid + 32) * 16);

        float c[8][4];
        #pragma unroll
        for (int nt = 0; nt < 8; nt++) {
            c[nt][0] = c[nt][1] = c[nt][2] = c[nt][3] = 0.f;
            mma_f16(c[nt], ah4, bh[nt], 0u);
        }

        // softmax numerators + row sums (fp32, exact)
        float sum0 = 0.f, sum1 = 0.f;
        #pragma unroll
        for (int nt = 0; nt < 8; nt++) {
            c[nt][0] = ex2(c[nt][0]); c[nt][1] = ex2(c[nt][1]);
            c[nt][2] = ex2(c[nt][2]); c[nt][3] = ex2(c[nt][3]);
            sum0 += c[nt][0] + c[nt][1];
            sum1 += c[nt][2] + c[nt][3];
        }
        sum0 += __shfl_xor_sync(0xffffffffu, sum0, 1);
        sum0 += __shfl_xor_sync(0xffffffffu, sum0, 2);
        sum1 += __shfl_xor_sync(0xffffffffu, sum1, 1);
        sum1 += __shfl_xor_sync(0xffffffffu, sum1, 2);
        const float inv0 = rcpa(sum0);
        const float inv1 = rcpa(sum1);

        // pack E into fp16 A-frags (C-frag -> A-frag layout identity)
        unsigned Eh[4][4];
        #pragma unroll
        for (int kt = 0; kt < 4; kt++) {
            const int n0 = 2 * kt, n1 = 2 * kt + 1;
            Eh[kt][0] = cvtf16x2(c[n0][1], c[n0][0]);
            Eh[kt][1] = cvtf16x2(c[n0][3], c[n0][2]);
            Eh[kt][2] = cvtf16x2(c[n1][1], c[n1][0]);
            Eh[kt][3] = cvtf16x2(c[n1][3], c[n1][2]);
        }

        // attn slice = E @ T   (16 x 8)
        float o[4] = {0.f, 0.f, 0.f, 0.f};
        #pragma unroll
        for (int kt = 0; kt < 4; kt++) {
            mma_f16(o, Eh[kt], bT[kt][0], bT[kt][1]);
        }
        o[0] *= inv0; o[1] *= inv0; o[2] *= inv1; o[3] *= inv1;

        // single fp16 store of mid (permuted layout)
        const int h0 = 16 * ms + (lid >> 2);
        const size_t off0 = (rowTail + (size_t)(h0 * 32)) * EDIM + colOff;
        const size_t off1 = (rowTail + (size_t)((h0 + 8) * 32)) * EDIM + colOff;
        *(unsigned*)(g_A + off0) = cvtf16x2(o[1], o[0]);
        *(unsigned*)(g_A + off1) = cvtf16x2(o[3], o[2]);
    }
}

// ---------------------------------------------------------------------------
// Kernel B: 1-term fp16 GEMM on mma.sync, 3-stage cp.async pipeline (R10).
// ---------------------------------------------------------------------------
#define TILE_B   8192
#define STAGE_B  16384
#define NSTAGE   3
#define NCHUNK   16
#define GSMEM_BYTES (NSTAGE * STAGE_B)
#define A_T 0
#define B_T 1

__device__ __forceinline__ void load_chunk(unsigned sb, int stage, int c,
                                           int rowBase, int colBase, int tid) {
    const unsigned base = sb + stage * STAGE_B;
    #pragma unroll
    for (int i = 0; i < 4; i++) {
        const int v    = i * 256 + tid;   // 0..1023
        const int tile = v >> 9;          // 512 v16 per tile (constant per i)
        const int rem  = v & 511;
        const int r    = rem >> 2;
        const int c16  = rem & 3;
        const unsigned short* src;
        if (tile == 0) src = g_A + (size_t)(rowBase + r) * EDIM;
        else           src = g_B + (size_t)(colBase + r) * EDIM;
        src += c * 32 + c16 * 8;
        cp16(base + tile * TILE_B + SWZ64(r * 64 + c16 * 16), src);
    }
    asm volatile("cp.async.commit_group;" ::: "memory");
}

__global__ __launch_bounds__(256, 2) void out_gemm_mma(const float* __restrict__ bias,
                                                       float* __restrict__ out) {
    extern __shared__ char smem[];
    const unsigned sb = smem_u32(smem);
    const int tid = threadIdx.x;
    const int wid = tid >> 5;
    const int lid = tid & 31;

    const int rowBase = blockIdx.y * 128;
    const int colBase = blockIdx.x * 128;

    const int wy = wid & 3;    // m: 32 rows each
    const int wx = wid >> 2;   // n: 64 cols each

    const int lr  = lid & 7;
    const int sub = lid >> 3;

    float acc[2][8][4];
    #pragma unroll
    for (int mt = 0; mt < 2; mt++)
        #pragma unroll
        for (int nt = 0; nt < 8; nt++)
            #pragma unroll
            for (int q = 0; q < 4; q++) acc[mt][nt][q] = 0.f;

    load_chunk(sb, 0, 0, rowBase, colBase, tid);
    load_chunk(sb, 1, 1, rowBase, colBase, tid);

    int stage = 0;
    for (int c = 0; c < NCHUNK; c++) {
        if (c < NCHUNK - 1) {
            asm volatile("cp.async.wait_group 1;" ::: "memory");
        } else {
            asm volatile("cp.async.wait_group 0;" ::: "memory");
        }
        __syncthreads();

        const unsigned stg = sb + (unsigned)stage * STAGE_B;

        #pragma unroll
        for (int kk = 0; kk < 2; kk++) {
            const int kb = kk * 32;

            unsigned ah[2][4];
            #pragma unroll
            for (int mt = 0; mt < 2; mt++) {
                const int rowA = wy * 32 + mt * 16 + lr + (sub & 1) * 8;
                const int colb = kb + (sub >> 1) * 16;
                const unsigned off = SWZ64(rowA * 64 + colb);
                ldsm_x4(ah[mt][0], ah[mt][1], ah[mt][2], ah[mt][3], stg + A_T * TILE_B + off);
            }

            unsigned bh[4][4];
            #pragma unroll
            for (int nt16 = 0; nt16 < 4; nt16++) {
                const int rowB = wx * 64 + nt16 * 16 + lr + (sub >> 1) * 8;
                const int colb = kb + (sub & 1) * 16;
                const unsigned off = SWZ64(rowB * 64 + colb);
                ldsm_x4(bh[nt16][0], bh[nt16][1], bh[nt16][2], bh[nt16][3], stg + B_T * TILE_B + off);
            }

            #pragma unroll
            for (int nt16 = 0; nt16 < 4; nt16++)
                #pragma unroll
                for (int mt = 0; mt < 2; mt++) {
                    mma_f16(acc[mt][nt16 * 2],     ah[mt], bh[nt16][0], bh[nt16][1]);
                    mma_f16(acc[mt][nt16 * 2 + 1], ah[mt], bh[nt16][2], bh[nt16][3]);
                }
        }

        if (c + 2 < NCHUNK) {
            int fs = stage + 2;
            if (fs >= NSTAGE) fs -= NSTAGE;
            load_chunk(sb, fs, c + 2, rowBase, colBase, tid);
        }
        if (++stage == NSTAGE) stage = 0;
    }

    // epilogue: bias + store
    const int qrow = lid >> 2;
    const int qcol = (lid & 3) * 2;
    #pragma unroll
    for (int mt = 0; mt < 2; mt++) {
        #pragma unroll
        for (int nt = 0; nt < 8; nt++) {
            const int row = rowBase + wy * 32 + mt * 16 + qrow;
            const int col = colBase + wx * 64 + nt * 8 + qcol;
            const float2 bv = *(const float2*)&bias[col];
            float* o0 = out + (size_t)row * EDIM + col;
            float* o1 = o0 + 8 * EDIM;
            *(float2*)o0 = make_float2(acc[mt][nt][0] + bv.x, acc[mt][nt][1] + bv.y);
            *(float2*)o1 = make_float2(acc[mt][nt][2] + bv.x, acc[mt][nt][3] + bv.y);
        }
    }
}

// ---------------------------------------------------------------------------
extern "C" void kernel_launch(void* const* d_in, const int* in_sizes, int n_in,
                              void* d_out, int out_size) {
    const float* x     = (const float*)d_in[0];
    const float* theta = (const float*)d_in[1];
    const float* W     = (const float*)d_in[2];
    const float* bias  = (const float*)d_in[3];
    float* out = (float*)d_out;

    cudaFuncSetAttribute(out_gemm_mma, cudaFuncAttributeMaxDynamicSharedMemorySize,
                         GSMEM_BYTES);

    qattn_tc<<<TOKENS / 8, 256>>>(x, theta, W);

    dim3 grid(EDIM / 128, TOKENS / 128);   // (4, 128)
    out_gemm_mma<<<grid, 256, GSMEM_BYTES>>>(bias, out);
}

// round 13
// speedup vs baseline: 20.1823x; 1.0435x over previous
#include <cuda_runtime.h>
#include <cuda_bf16.h>
#include <math_constants.h>

#define TOKENS (8 * 2048)
#define EDIM   512
#define NHEAD  64
#define DK     8

// fp16 operands for the output GEMM (1-term: fp16 quantization 2^-12 is enough)
__device__ unsigned short g_A[(size_t)TOKENS * EDIM];   // mid, fp16
__device__ unsigned short g_B[(size_t)EDIM * EDIM];     // W,  fp16

// ---- helpers --------------------------------------------------------------
__device__ __forceinline__ float ex2(float x) {
    float y; asm("ex2.approx.f32 %0, %1;" : "=f"(y) : "f"(x)); return y;
}
__device__ __forceinline__ float rcpa(float x) {
    float y; asm("rcp.approx.f32 %0, %1;" : "=f"(y) : "f"(x)); return y;
}
__device__ __forceinline__ unsigned cvtf16x2(float hi_, float lo_) {
    unsigned d;
    asm("cvt.rn.f16x2.f32 %0, %1, %2;" : "=r"(d) : "f"(hi_), "f"(lo_));
    return d;
}
__device__ __forceinline__ unsigned smem_u32(const void* p) {
    unsigned a;
    asm("{ .reg .u64 t; cvta.to.shared.u64 t, %1; cvt.u32.u64 %0, t; }" : "=r"(a) : "l"(p));
    return a;
}
__device__ __forceinline__ void cp16(unsigned dst, const void* src) {
    asm volatile("cp.async.cg.shared.global [%0], [%1], 16;" :: "r"(dst), "l"(src));
}
__device__ __forceinline__ void ldsm_x4(unsigned& r0, unsigned& r1, unsigned& r2,
                                        unsigned& r3, unsigned addr) {
    asm volatile("ldmatrix.sync.aligned.m8n8.x4.shared.b16 {%0,%1,%2,%3}, [%4];"
                 : "=r"(r0), "=r"(r1), "=r"(r2), "=r"(r3) : "r"(addr));
}
__device__ __forceinline__ void ldsm_x2(unsigned& r0, unsigned& r1, unsigned addr) {
    asm volatile("ldmatrix.sync.aligned.m8n8.x2.shared.b16 {%0,%1}, [%2];"
                 : "=r"(r0), "=r"(r1) : "r"(addr));
}
__device__ __forceinline__ void mma_f16(float* c, const unsigned* a,
                                        unsigned b0, unsigned b1) {
    asm volatile("mma.sync.aligned.m16n8k16.row.col.f32.f16.f16.f32 "
                 "{%0,%1,%2,%3}, {%4,%5,%6,%7}, {%8,%9}, {%0,%1,%2,%3};"
                 : "+f"(c[0]), "+f"(c[1]), "+f"(c[2]), "+f"(c[3])
                 : "r"(a[0]), "r"(a[1]), "r"(a[2]), "r"(a[3]), "r"(b0), "r"(b1));
}

#define SWZ64(o) ((o) ^ (((o) >> 3) & 0x30))

// ---------------------------------------------------------------------------
// Kernel A: tensor-core quantum attention, ALL-fp16 1-term (unchanged R11).
// ---------------------------------------------------------------------------
#define TOK_SZ 2304
#define PH_OFF 0
#define TH_OFF 1024

__global__ __launch_bounds__(256, 2) void qattn_tc(const float* __restrict__ x,
                                                   const float* __restrict__ theta,
                                                   const float* __restrict__ W) {
    __shared__ char sm[8 * TOK_SZ];

    const int tid = threadIdx.x;
    const int wid = tid >> 5;
    const int lid = tid & 31;

    // Folded W conversion to fp16
    if (blockIdx.x < 256) {
        const int idx = blockIdx.x * 256 + tid;
        const float4 w = ((const float4*)W)[idx];
        uint2 hu;
        hu.x = cvtf16x2(w.y, w.x);
        hu.y = cvtf16x2(w.w, w.z);
        ((uint2*)g_B)[idx] = hu;
    }

    const int token = blockIdx.x * 8 + wid;
    const unsigned base = smem_u32(sm) + wid * TOK_SZ;
    char* smp = sm + wid * TOK_SZ;

    float th[8];
    {
        const float4 t0 = ((const float4*)theta)[0];
        const float4 t1 = ((const float4*)theta)[1];
        th[0] = t0.x; th[1] = t0.y; th[2] = t0.z; th[3] = t0.w;
        th[4] = t1.x; th[5] = t1.y; th[6] = t1.z; th[7] = t1.w;
    }

    const float s = 0.7142224053f;   // sqrt((1/sqrt8)*log2e)

    {
        const float* xb = x + (size_t)token * EDIM + lid * 16;
        const float4 v0 = ((const float4*)xb)[0];
        const float4 v1 = ((const float4*)xb)[1];
        const float4 v2 = ((const float4*)xb)[2];
        const float4 v3 = ((const float4*)xb)[3];
        float pa[8], pb[8];
        pa[0] = __cosf(v0.x + th[0]); pa[1] = __cosf(v0.y + th[1]);
        pa[2] = __cosf(v0.z + th[2]); pa[3] = __cosf(v0.w + th[3]);
        pa[4] = __cosf(v1.x + th[4]); pa[5] = __cosf(v1.y + th[5]);
        pa[6] = __cosf(v1.z + th[6]); pa[7] = __cosf(v1.w + th[7]);
        pb[0] = __cosf(v2.x + th[0]); pb[1] = __cosf(v2.y + th[1]);
        pb[2] = __cosf(v2.z + th[2]); pb[3] = __cosf(v2.w + th[3]);
        pb[4] = __cosf(v3.x + th[4]); pb[5] = __cosf(v3.y + th[5]);
        pb[6] = __cosf(v3.z + th[6]); pb[7] = __cosf(v3.w + th[7]);

        #pragma unroll
        for (int d = 0; d < 8; d++) {
            *(unsigned*)(smp + TH_OFF + d * 144 + lid * 4) = cvtf16x2(pb[d], pa[d]);
        }

        uint4 row;
        row.x = cvtf16x2(pa[1] * s, pa[0] * s);
        row.y = cvtf16x2(pa[3] * s, pa[2] * s);
        row.z = cvtf16x2(pa[5] * s, pa[4] * s);
        row.w = cvtf16x2(pa[7] * s, pa[6] * s);
        *(uint4*)(smp + PH_OFF + (2 * lid) * 16) = row;
        row.x = cvtf16x2(pb[1] * s, pb[0] * s);
        row.y = cvtf16x2(pb[3] * s, pb[2] * s);
        row.z = cvtf16x2(pb[5] * s, pb[4] * s);
        row.w = cvtf16x2(pb[7] * s, pb[6] * s);
        *(uint4*)(smp + PH_OFF + (2 * lid + 1) * 16) = row;
    }
    __syncwarp();

    unsigned bT[4][2];
    #pragma unroll
    for (int t = 0; t < 2; t++) {
        const unsigned addrh = base + TH_OFF + (lid & 7) * 144 + t * 64 + (lid >> 3) * 16;
        ldsm_x4(bT[2 * t][0], bT[2 * t][1], bT[2 * t + 1][0], bT[2 * t + 1][1], addrh);
    }

    const int bI  = token >> 11;
    const int sbI = token & 2047;
    const size_t rowTail = (size_t)(bI * 2048) + (size_t)(sbI >> 6);
    const int colOff = (sbI & 63) * DK + 2 * (lid & 3);

    #pragma unroll 1
    for (int ms = 0; ms < 4; ms++) {
        unsigned ah4[4] = {0u, 0u, 0u, 0u};
        ldsm_x2(ah4[0], ah4[1], base + PH_OFF + (16 * ms + (lid & 15)) * 16);

        unsigned bh[8];
        ldsm_x4(bh[0], bh[1], bh[2], bh[3], base + PH_OFF + lid * 16);
        ldsm_x4(bh[4], bh[5], bh[6], bh[7], base + PH_OFF + (lid + 32) * 16);

        float c[8][4];
        #pragma unroll
        for (int nt = 0; nt < 8; nt++) {
            c[nt][0] = c[nt][1] = c[nt][2] = c[nt][3] = 0.f;
            mma_f16(c[nt], ah4, bh[nt], 0u);
        }

        float sum0 = 0.f, sum1 = 0.f;
        #pragma unroll
        for (int nt = 0; nt < 8; nt++) {
            c[nt][0] = ex2(c[nt][0]); c[nt][1] = ex2(c[nt][1]);
            c[nt][2] = ex2(c[nt][2]); c[nt][3] = ex2(c[nt][3]);
            sum0 += c[nt][0] + c[nt][1];
            sum1 += c[nt][2] + c[nt][3];
        }
        sum0 += __shfl_xor_sync(0xffffffffu, sum0, 1);
        sum0 += __shfl_xor_sync(0xffffffffu, sum0, 2);
        sum1 += __shfl_xor_sync(0xffffffffu, sum1, 1);
        sum1 += __shfl_xor_sync(0xffffffffu, sum1, 2);
        const float inv0 = rcpa(sum0);
        const float inv1 = rcpa(sum1);

        unsigned Eh[4][4];
        #pragma unroll
        for (int kt = 0; kt < 4; kt++) {
            const int n0 = 2 * kt, n1 = 2 * kt + 1;
            Eh[kt][0] = cvtf16x2(c[n0][1], c[n0][0]);
            Eh[kt][1] = cvtf16x2(c[n0][3], c[n0][2]);
            Eh[kt][2] = cvtf16x2(c[n1][1], c[n1][0]);
            Eh[kt][3] = cvtf16x2(c[n1][3], c[n1][2]);
        }

        float o[4] = {0.f, 0.f, 0.f, 0.f};
        #pragma unroll
        for (int kt = 0; kt < 4; kt++) {
            mma_f16(o, Eh[kt], bT[kt][0], bT[kt][1]);
        }
        o[0] *= inv0; o[1] *= inv0; o[2] *= inv1; o[3] *= inv1;

        const int h0 = 16 * ms + (lid >> 2);
        const size_t off0 = (rowTail + (size_t)(h0 * 32)) * EDIM + colOff;
        const size_t off1 = (rowTail + (size_t)((h0 + 8) * 32)) * EDIM + colOff;
        *(unsigned*)(g_A + off0) = cvtf16x2(o[1], o[0]);
        *(unsigned*)(g_A + off1) = cvtf16x2(o[3], o[2]);
    }
}

// ---------------------------------------------------------------------------
// Kernel B: 1-term fp16 GEMM, 3-stage cp.async pipeline, 4 warps / 128 thr,
// warp tile 64x64 (2x2 warp grid): per kk, 8 ldsm_x4 (32 crossbar cyc) serve
// 32 HMMA (64 tensor cyc) -> tensor-limited with 2x crossbar slack.
// ---------------------------------------------------------------------------
#define TILE_B   8192
#define STAGE_B  16384
#define NSTAGE   3
#define NCHUNK   16
#define GSMEM_BYTES (NSTAGE * STAGE_B)
#define A_T 0
#define B_T 1

__device__ __forceinline__ void load_chunk(unsigned sb, int stage, int c,
                                           int rowBase, int colBase, int tid) {
    const unsigned base = sb + stage * STAGE_B;
    #pragma unroll
    for (int i = 0; i < 8; i++) {
        const int v    = i * 128 + tid;   // 0..1023
        const int tile = v >> 9;          // 512 v16 per tile (constant per i)
        const int rem  = v & 511;
        const int r    = rem >> 2;
        const int c16  = rem & 3;
        const unsigned short* src;
        if (tile == 0) src = g_A + (size_t)(rowBase + r) * EDIM;
        else           src = g_B + (size_t)(colBase + r) * EDIM;
        src += c * 32 + c16 * 8;
        cp16(base + tile * TILE_B + SWZ64(r * 64 + c16 * 16), src);
    }
    asm volatile("cp.async.commit_group;" ::: "memory");
}

__global__ __launch_bounds__(128, 2) void out_gemm_mma(const float* __restrict__ bias,
                                                       float* __restrict__ out) {
    extern __shared__ char smem[];
    const unsigned sb = smem_u32(smem);
    const int tid = threadIdx.x;
    const int wid = tid >> 5;
    const int lid = tid & 31;

    const int rowBase = blockIdx.y * 128;
    const int colBase = blockIdx.x * 128;

    const int wy = wid & 1;    // m: 64 rows
    const int wx = wid >> 1;   // n: 64 cols

    const int lr  = lid & 7;
    const int sub = lid >> 3;

    float acc[4][8][4];
    #pragma unroll
    for (int mt = 0; mt < 4; mt++)
        #pragma unroll
        for (int nt = 0; nt < 8; nt++)
            #pragma unroll
            for (int q = 0; q < 4; q++) acc[mt][nt][q] = 0.f;

    load_chunk(sb, 0, 0, rowBase, colBase, tid);
    load_chunk(sb, 1, 1, rowBase, colBase, tid);

    int stage = 0;
    for (int c = 0; c < NCHUNK; c++) {
        if (c < NCHUNK - 1) {
            asm volatile("cp.async.wait_group 1;" ::: "memory");
        } else {
            asm volatile("cp.async.wait_group 0;" ::: "memory");
        }
        __syncthreads();

        const unsigned stg = sb + (unsigned)stage * STAGE_B;

        #pragma unroll
        for (int kk = 0; kk < 2; kk++) {
            const int kb = kk * 32;

            // A frags for 64 rows (4 m16 tiles)
            unsigned ah[4][4];
            #pragma unroll
            for (int mt = 0; mt < 4; mt++) {
                const int rowA = wy * 64 + mt * 16 + lr + (sub & 1) * 8;
                const int colb = kb + (sub >> 1) * 16;
                const unsigned off = SWZ64(rowA * 64 + colb);
                ldsm_x4(ah[mt][0], ah[mt][1], ah[mt][2], ah[mt][3], stg + A_T * TILE_B + off);
            }

            // B frags for 64 cols (4 n16 tiles)
            unsigned bh[4][4];
            #pragma unroll
            for (int nt16 = 0; nt16 < 4; nt16++) {
                const int rowB = wx * 64 + nt16 * 16 + lr + (sub >> 1) * 8;
                const int colb = kb + (sub & 1) * 16;
                const unsigned off = SWZ64(rowB * 64 + colb);
                ldsm_x4(bh[nt16][0], bh[nt16][1], bh[nt16][2], bh[nt16][3], stg + B_T * TILE_B + off);
            }

            #pragma unroll
            for (int nt16 = 0; nt16 < 4; nt16++)
                #pragma unroll
                for (int mt = 0; mt < 4; mt++) {
                    mma_f16(acc[mt][nt16 * 2],     ah[mt], bh[nt16][0], bh[nt16][1]);
                    mma_f16(acc[mt][nt16 * 2 + 1], ah[mt], bh[nt16][2], bh[nt16][3]);
                }
        }

        if (c + 2 < NCHUNK) {
            int fs = stage + 2;
            if (fs >= NSTAGE) fs -= NSTAGE;
            load_chunk(sb, fs, c + 2, rowBase, colBase, tid);
        }
        if (++stage == NSTAGE) stage = 0;
    }

    // epilogue: bias + store
    const int qrow = lid >> 2;
    const int qcol = (lid & 3) * 2;
    #pragma unroll
    for (int mt = 0; mt < 4; mt++) {
        #pragma unroll
        for (int nt = 0; nt < 8; nt++) {
            const int row = rowBase + wy * 64 + mt * 16 + qrow;
            const int col = colBase + wx * 64 + nt * 8 + qcol;
            const float2 bv = *(const float2*)&bias[col];
            float* o0 = out + (size_t)row * EDIM + col;
            float* o1 = o0 + 8 * EDIM;
            *(float2*)o0 = make_float2(acc[mt][nt][0] + bv.x, acc[mt][nt][1] + bv.y);
            *(float2*)o1 = make_float2(acc[mt][nt][2] + bv.x, acc[mt][nt][3] + bv.y);
        }
    }
}

// ---------------------------------------------------------------------------
extern "C" void kernel_launch(void* const* d_in, const int* in_sizes, int n_in,
                              void* d_out, int out_size) {
    const float* x     = (const float*)d_in[0];
    const float* theta = (const float*)d_in[1];
    const float* W     = (const float*)d_in[2];
    const float* bias  = (const float*)d_in[3];
    float* out = (float*)d_out;

    cudaFuncSetAttribute(out_gemm_mma, cudaFuncAttributeMaxDynamicSharedMemorySize,
                         GSMEM_BYTES);

    qattn_tc<<<TOKENS / 8, 256>>>(x, theta, W);

    dim3 grid(EDIM / 128, TOKENS / 128);   // (4, 128)
    out_gemm_mma<<<grid, 128, GSMEM_BYTES>>>(bias, out);
}